// round 1
// baseline (speedup 1.0000x reference)
#include <cuda_runtime.h>
#include <cmath>
#include <cstdint>

// ======================= model constants =======================
#define Nn    2
#define Mm_   2
#define NM    4
#define Cin   3
#define Tt    100
#define Vv    25
#define Kk    13
#define C1    96
#define C2    192
#define S1n   50
#define S2n   30
#define IN1   4752     // 2*96 + 4560
#define IN2   18720    // 2*192 + 18336
#define P1    4560
#define P2    18336
#define NCLS  60

struct Seg { int starts[64]; int ends[64]; };

// ======================= device scratch ========================
__device__ float g_h0[NM*Tt*Vv*Cin];          // 30000
__device__ float g_stat0[150*2];
__device__ float g_S1[NM*Tt*Vv*Kk*Cin];       // 390000
__device__ float g_O1[NM*Tt*Vv*C1];           // 960000
__device__ float g_stat1[C1*2];
__device__ float g_seq1[100*Tt*C1];           // 960000
__device__ float g_feats1[5000*IN1];          // 23.76M
__device__ float g_xp1[5000*4*C1];
__device__ float g_WT1[C1*4*C1];
__device__ float g_y1[100*S1n*C1];
__device__ float g_sstat1[S1n*2];
__device__ float g_h1b[NM*S1n*Vv*C1];         // 480000
__device__ float g_S2[NM*S1n*Vv*Kk*C1];       // 6.24M
__device__ float g_O2[NM*S1n*Vv*C2];          // 960000
__device__ float g_stat2[C2*2];
__device__ float g_seq2[100*S1n*C2];          // 960000
__device__ float g_feats2[3000*IN2];          // 56.16M
__device__ float g_xp2[3000*4*C2];
__device__ float g_WT2[C2*4*C2];
__device__ float g_y2[100*S2n*C2];
__device__ float g_sstat2[S2n*2];

// ======================= kernels ===============================

// WT[k*G + j] = W[j*H + k]   (W is (G,H) row-major, G=4H)
__global__ void k_transpose(const float* __restrict__ W, float* __restrict__ WT, int G, int H) {
    int idx = blockIdx.x * blockDim.x + threadIdx.x;
    if (idx < G * H) {
        int j = idx / H, k = idx % H;
        WT[k * G + j] = W[j * H + k];
    }
}

// data_bn stats: channel ch = m*75 + v*3 + c over (n,t) -> 200 values
__global__ void k_bn0_stats(const float* __restrict__ x, float* __restrict__ stat) {
    int ch = blockIdx.x;
    int m = ch / (Vv * Cin);
    int v = (ch / Cin) % Vv;
    int c = ch % Cin;
    double s = 0.0, ss = 0.0;
    for (int i = threadIdx.x; i < Nn * Tt; i += blockDim.x) {
        int n = i / Tt, t = i % Tt;
        float val = x[(((n * Cin + c) * Tt + t) * Vv + v) * Mm_ + m];
        s += val; ss += (double)val * val;
    }
    __shared__ double r1[256], r2[256];
    r1[threadIdx.x] = s; r2[threadIdx.x] = ss;
    __syncthreads();
    for (int off = 128; off > 0; off >>= 1) {
        if (threadIdx.x < off) { r1[threadIdx.x] += r1[threadIdx.x + off]; r2[threadIdx.x] += r2[threadIdx.x + off]; }
        __syncthreads();
    }
    if (threadIdx.x == 0) {
        double cnt = (double)(Nn * Tt);
        double mean = r1[0] / cnt;
        double var = r2[0] / cnt - mean * mean;
        if (var < 0.0) var = 0.0;
        stat[2 * ch] = (float)mean;
        stat[2 * ch + 1] = (float)(1.0 / sqrt(var + 1e-5));
    }
}

// apply data_bn, output layout h0[nm][t][v][c]
__global__ void k_bn0_apply(const float* __restrict__ x, const float* __restrict__ stat,
                            const float* __restrict__ g, const float* __restrict__ b,
                            float* __restrict__ h0) {
    int idx = blockIdx.x * blockDim.x + threadIdx.x;
    if (idx >= NM * Tt * Vv * Cin) return;
    int c = idx % Cin;
    int v = (idx / Cin) % Vv;
    int t = (idx / (Cin * Vv)) % Tt;
    int nm = idx / (Cin * Vv * Tt);
    int n = nm >> 1, m = nm & 1;
    int ch = m * (Vv * Cin) + v * Cin + c;
    float val = x[(((n * Cin + c) * Tt + t) * Vv + v) * Mm_ + m];
    h0[idx] = (val - stat[2 * ch]) * stat[2 * ch + 1] * g[ch] + b[ch];
}

// support: Sout[((nm*T+t)*25+v)*(13*Cc) + k*Cc + c] = sum_u A[k*25+v,u]*hin[nm][t][u][c]
__global__ void k_gcn_support(const float* __restrict__ hin, const float* __restrict__ Ap,
                              const float* __restrict__ Ares, float* __restrict__ Sout,
                              int T, int Cc) {
    __shared__ float Asm[325 * 25];
    extern __shared__ float hsm[];
    int blk = blockIdx.x;            // nm*T + t
    for (int i = threadIdx.x; i < 325 * 25; i += blockDim.x) Asm[i] = Ap[i] + Ares[i];
    const float* hrow = hin + (size_t)blk * Vv * Cc;
    for (int i = threadIdx.x; i < Vv * Cc; i += blockDim.x) hsm[i] = hrow[i];
    __syncthreads();
    int tot = Vv * Kk * Cc;
    float* outrow = Sout + (size_t)blk * tot;
    for (int f = threadIdx.x; f < tot; f += blockDim.x) {
        int c = f % Cc;
        int k = (f / Cc) % Kk;
        int v = f / (Kk * Cc);
        const float* arow = Asm + (k * Vv + v) * Vv;
        float acc = 0.f;
        #pragma unroll
        for (int u = 0; u < Vv; u++) acc += arow[u] * hsm[u * Cc + c];
        outrow[f] = acc;
    }
}

// C[M,N] = A[M,K] * B[N,K]^T + bias1 + bias2  (row-major)
#define TBM 64
#define TBN 64
#define TBK 16
__global__ void k_gemm_abt(const float* __restrict__ A, const float* __restrict__ B,
                           const float* __restrict__ bias1, const float* __restrict__ bias2,
                           float* __restrict__ C, int M, int N, int K) {
    __shared__ float As[TBK][TBM];
    __shared__ float Bs[TBK][TBN];
    int m0 = blockIdx.y * TBM;
    int n0 = blockIdx.x * TBN;
    int tid = threadIdx.x;
    int tx = tid & 15, ty = tid >> 4;
    float acc[4][4] = {};
    for (int kt = 0; kt < K; kt += TBK) {
        #pragma unroll
        for (int e = 0; e < 4; e++) {
            int idx = tid + e * 256;
            int r = idx >> 4, c = idx & 15;
            int gk = kt + c;
            int gm = m0 + r;
            As[c][r] = (gm < M && gk < K) ? A[(size_t)gm * K + gk] : 0.f;
            int gn = n0 + r;
            Bs[c][r] = (gn < N && gk < K) ? B[(size_t)gn * K + gk] : 0.f;
        }
        __syncthreads();
        #pragma unroll
        for (int kk = 0; kk < TBK; kk++) {
            float4 a4 = *reinterpret_cast<const float4*>(&As[kk][ty * 4]);
            float4 b4 = *reinterpret_cast<const float4*>(&Bs[kk][tx * 4]);
            float av[4] = {a4.x, a4.y, a4.z, a4.w};
            float bv[4] = {b4.x, b4.y, b4.z, b4.w};
            #pragma unroll
            for (int r = 0; r < 4; r++)
                #pragma unroll
                for (int c = 0; c < 4; c++) acc[r][c] += av[r] * bv[c];
        }
        __syncthreads();
    }
    #pragma unroll
    for (int r = 0; r < 4; r++) {
        int gm = m0 + ty * 4 + r;
        if (gm >= M) continue;
        #pragma unroll
        for (int c = 0; c < 4; c++) {
            int gn = n0 + tx * 4 + c;
            if (gn >= N) continue;
            float bv = (bias1 ? bias1[gn] : 0.f) + (bias2 ? bias2[gn] : 0.f);
            C[(size_t)gm * N + gn] = acc[r][c] + bv;
        }
    }
}

// per-column stats over rows: X (Mrows, Ncols), one block per column
__global__ void k_colstats(const float* __restrict__ X, float* __restrict__ stat, int Mrows, int Ncols) {
    int col = blockIdx.x;
    double s = 0.0, ss = 0.0;
    for (int r = threadIdx.x; r < Mrows; r += blockDim.x) {
        float v = X[(size_t)r * Ncols + col];
        s += v; ss += (double)v * v;
    }
    __shared__ double r1[256], r2[256];
    r1[threadIdx.x] = s; r2[threadIdx.x] = ss;
    __syncthreads();
    for (int off = 128; off > 0; off >>= 1) {
        if (threadIdx.x < off) { r1[threadIdx.x] += r1[threadIdx.x + off]; r2[threadIdx.x] += r2[threadIdx.x + off]; }
        __syncthreads();
    }
    if (threadIdx.x == 0) {
        double cnt = (double)Mrows;
        double mean = r1[0] / cnt;
        double var = r2[0] / cnt - mean * mean;
        if (var < 0.0) var = 0.0;
        stat[2 * col] = (float)mean;
        stat[2 * col + 1] = (float)(1.0 / sqrt(var + 1e-5));
    }
}

// BN + relu + transpose to sequence layout: seq[(nm*V+v)*T + t][c] from O[(nm*T+t)*V+v][c]
__global__ void k_bn_relu_seq(const float* __restrict__ O, const float* __restrict__ stat,
                              const float* __restrict__ g, const float* __restrict__ bb,
                              float* __restrict__ seq, int T, int Cc, int total) {
    int idx = blockIdx.x * blockDim.x + threadIdx.x;
    if (idx >= total) return;
    int c = idx % Cc;
    int j = idx / Cc;
    int v = j % Vv;
    int t = (j / Vv) % T;
    int nm = j / (Vv * T);
    float val = (O[idx] - stat[2 * c]) * stat[2 * c + 1] * g[c] + bb[c];
    val = fmaxf(val, 0.f);
    int b = nm * Vv + v;
    seq[((size_t)b * T + t) * Cc + c] = val;
}

// log-signature features: feats[b*S+s] = [pts0 (d), inc (d), levy (d(d-1)/2)]
__global__ void k_feats(const float* __restrict__ seq, float* __restrict__ feats,
                        int T, int d, int S, int L, int in_dim, Seg seg) {
    __shared__ float s_pts[4][192];
    __shared__ float s_rel[3][192];
    __shared__ float s_dx[3][192];
    int bs = blockIdx.x;
    int b = bs / S, s = bs % S;
    const float* xb = seq + (size_t)b * T * d;
    for (int l = 0; l < L; l++) {
        int idx = seg.starts[s] + l;
        if (idx > seg.ends[s]) idx = seg.ends[s];
        for (int i = threadIdx.x; i < d; i += blockDim.x) s_pts[l][i] = xb[(size_t)idx * d + i];
    }
    __syncthreads();
    float* out = feats + (size_t)bs * in_dim;
    for (int i = threadIdx.x; i < d; i += blockDim.x) {
        float p0 = s_pts[0][i];
        for (int l = 0; l + 1 < L; l++) {
            s_rel[l][i] = s_pts[l][i] - p0;
            s_dx[l][i] = s_pts[l + 1][i] - s_pts[l][i];
        }
        out[i] = p0;
        out[d + i] = s_pts[L - 1][i] - p0;
    }
    __syncthreads();
    int Lm1 = L - 1;
    for (int i = threadIdx.x; i < d - 1; i += blockDim.x) {
        int base = 2 * d + i * (2 * d - i - 1) / 2;
        float ri[3], di[3];
        for (int l = 0; l < Lm1; l++) { ri[l] = s_rel[l][i]; di[l] = s_dx[l][i]; }
        for (int j = i + 1; j < d; j++) {
            float acc = 0.f;
            for (int l = 0; l < Lm1; l++) acc += ri[l] * s_dx[l][j] - s_rel[l][j] * di[l];
            out[base + (j - i - 1)] = 0.5f * acc;
        }
    }
}

__device__ __forceinline__ float sigf(float x) { return 1.f / (1.f + expf(-x)); }

// persistent per-sequence LSTM. block b, threads = 4H. WT is (H, 4H) row-major.
__global__ void k_lstm(const float* __restrict__ xp, const float* __restrict__ WT,
                       float* __restrict__ y, int S, int H, int stageW) {
    extern __shared__ float sm[];
    float* sh = sm;
    float* sc = sm + H;
    float* sg = sm + 2 * H;
    float* sW = sm + 6 * H;
    int b = blockIdx.x;
    int j = threadIdx.x;
    int G = 4 * H;
    if (stageW) {
        for (int idx = j; idx < H * G; idx += blockDim.x) sW[idx] = WT[idx];
    }
    if (j < H) { sh[j] = 0.f; sc[j] = 0.f; }
    __syncthreads();
    const float* W = stageW ? sW : WT;
    for (int s = 0; s < S; s++) {
        float g = xp[((size_t)b * S + s) * G + j];
        for (int k = 0; k < H; k++) g += sh[k] * W[k * G + j];
        sg[j] = g;
        __syncthreads();
        if (j < H) {
            float iv = sigf(sg[j]);
            float fv = sigf(sg[H + j]);
            float gv = tanhf(sg[2 * H + j]);
            float ov = sigf(sg[3 * H + j]);
            float cn = fv * sc[j] + iv * gv;
            sc[j] = cn;
            float hn = ov * tanhf(cn);
            sh[j] = hn;
            y[((size_t)b * S + s) * H + j] = hn;
        }
        __syncthreads();
    }
}

// per-segment BN stats over (b, h): y (B=100, S, H)
__global__ void k_seg_stats(const float* __restrict__ y, float* __restrict__ stat, int S, int H) {
    int s = blockIdx.x;
    double sum = 0.0, ssq = 0.0;
    for (int i = threadIdx.x; i < 100 * H; i += blockDim.x) {
        int b = i / H, h = i % H;
        float v = y[((size_t)b * S + s) * H + h];
        sum += v; ssq += (double)v * v;
    }
    __shared__ double r1[256], r2[256];
    r1[threadIdx.x] = sum; r2[threadIdx.x] = ssq;
    __syncthreads();
    for (int off = 128; off > 0; off >>= 1) {
        if (threadIdx.x < off) { r1[threadIdx.x] += r1[threadIdx.x + off]; r2[threadIdx.x] += r2[threadIdx.x + off]; }
        __syncthreads();
    }
    if (threadIdx.x == 0) {
        double cnt = 100.0 * H;
        double mean = r1[0] / cnt;
        double var = r2[0] / cnt - mean * mean;
        if (var < 0.0) var = 0.0;
        stat[2 * s] = (float)mean;
        stat[2 * s + 1] = (float)(1.0 / sqrt(var + 1e-5));
    }
}

// seg BN apply + relayout: hout[((nm*S+s)*V+v)*H + c] from y[(nm*V+v)*S+s][c]
__global__ void k_seg_apply(const float* __restrict__ y, const float* __restrict__ stat,
                            const float* __restrict__ g, const float* __restrict__ bb,
                            float* __restrict__ hout, int S, int H, int total) {
    int idx = blockIdx.x * blockDim.x + threadIdx.x;
    if (idx >= total) return;
    int c = idx % H;
    int r = idx / H;
    int v = r % Vv;
    int s = (r / Vv) % S;
    int nm = r / (Vv * S);
    int b = nm * Vv + v;
    float val = (y[((size_t)b * S + s) * H + c] - stat[2 * s]) * stat[2 * s + 1] * g[s] + bb[s];
    hout[idx] = val;
}

// final: seg-BN (stats precomputed) + mean pooling + fc.  block per n.
__global__ void k_final(const float* __restrict__ y2, const float* __restrict__ stat,
                        const float* __restrict__ g, const float* __restrict__ bb,
                        const float* __restrict__ fcW, const float* __restrict__ fcb,
                        float* __restrict__ out) {
    __shared__ float pooled[C2];
    int n = blockIdx.x;
    for (int o = threadIdx.x; o < C2; o += blockDim.x) {
        float acc = 0.f;
        for (int m = 0; m < 2; m++)
            for (int v = 0; v < Vv; v++) {
                int b = (n * 2 + m) * Vv + v;
                for (int s = 0; s < S2n; s++) {
                    float val = (y2[((size_t)b * S2n + s) * C2 + o] - stat[2 * s]) * stat[2 * s + 1] * g[s] + bb[s];
                    acc += val;
                }
            }
        pooled[o] = acc / (2.f * Vv * S2n);
    }
    __syncthreads();
    for (int cls = threadIdx.x; cls < NCLS; cls += blockDim.x) {
        float acc = fcb[cls];
        for (int o = 0; o < C2; o++) acc += pooled[o] * fcW[cls * C2 + o];
        out[n * NCLS + cls] = acc;
    }
}

// ======================= host =======================

static void make_segs(int T, int S, Seg& seg, int& L) {
    // replicate np.linspace(1, T, S+1) (float64) + Python banker's round
    double delta = (double)(T - 1) / (double)S;
    int tv[65];
    for (int i = 0; i <= S; i++) {
        double v = 1.0 + delta * (double)i;
        tv[i] = (int)nearbyint(v);   // round-half-to-even (FE_TONEAREST)
    }
    tv[S] = T;                       // numpy sets endpoint exactly
    L = 0;
    for (int s = 0; s < S; s++) {
        seg.starts[s] = tv[s] - 1;
        seg.ends[s] = tv[s + 1] - 1;
        int len = seg.ends[s] - seg.starts[s] + 1;
        if (len > L) L = len;
    }
    if (L > 4) L = 4;
}

extern "C" void kernel_launch(void* const* d_in, const int* in_sizes, int n_in,
                              void* d_out, int out_size) {
    (void)in_sizes; (void)n_in; (void)out_size;
    const float* x        = (const float*)d_in[0];
    // d_in[1] = length (unused by reference)
    const float* dbn_g    = (const float*)d_in[2];
    const float* dbn_b    = (const float*)d_in[3];
    const float* Ap1      = (const float*)d_in[4];
    const float* Ar1      = (const float*)d_in[5];
    const float* W1       = (const float*)d_in[6];
    const float* b1       = (const float*)d_in[7];
    const float* bn1_g    = (const float*)d_in[8];
    const float* bn1_b    = (const float*)d_in[9];
    const float* Wih1     = (const float*)d_in[10];
    const float* Whh1     = (const float*)d_in[11];
    const float* bih1     = (const float*)d_in[12];
    const float* bhh1     = (const float*)d_in[13];
    const float* bs1_g    = (const float*)d_in[14];
    const float* bs1_b    = (const float*)d_in[15];
    const float* Ap2      = (const float*)d_in[16];
    const float* Ar2      = (const float*)d_in[17];
    const float* W2       = (const float*)d_in[18];
    const float* b2       = (const float*)d_in[19];
    const float* bn2_g    = (const float*)d_in[20];
    const float* bn2_b    = (const float*)d_in[21];
    const float* Wih2     = (const float*)d_in[22];
    const float* Whh2     = (const float*)d_in[23];
    const float* bih2     = (const float*)d_in[24];
    const float* bhh2     = (const float*)d_in[25];
    const float* bs2_g    = (const float*)d_in[26];
    const float* bs2_b    = (const float*)d_in[27];
    const float* fcW      = (const float*)d_in[28];
    const float* fcb      = (const float*)d_in[29];
    float* out = (float*)d_out;

    float *p_h0, *p_stat0, *p_S1, *p_O1, *p_stat1, *p_seq1, *p_f1, *p_xp1, *p_WT1, *p_y1,
          *p_ss1, *p_h1b, *p_S2, *p_O2, *p_stat2, *p_seq2, *p_f2, *p_xp2, *p_WT2, *p_y2, *p_ss2;
    cudaGetSymbolAddress((void**)&p_h0, g_h0);
    cudaGetSymbolAddress((void**)&p_stat0, g_stat0);
    cudaGetSymbolAddress((void**)&p_S1, g_S1);
    cudaGetSymbolAddress((void**)&p_O1, g_O1);
    cudaGetSymbolAddress((void**)&p_stat1, g_stat1);
    cudaGetSymbolAddress((void**)&p_seq1, g_seq1);
    cudaGetSymbolAddress((void**)&p_f1, g_feats1);
    cudaGetSymbolAddress((void**)&p_xp1, g_xp1);
    cudaGetSymbolAddress((void**)&p_WT1, g_WT1);
    cudaGetSymbolAddress((void**)&p_y1, g_y1);
    cudaGetSymbolAddress((void**)&p_ss1, g_sstat1);
    cudaGetSymbolAddress((void**)&p_h1b, g_h1b);
    cudaGetSymbolAddress((void**)&p_S2, g_S2);
    cudaGetSymbolAddress((void**)&p_O2, g_O2);
    cudaGetSymbolAddress((void**)&p_stat2, g_stat2);
    cudaGetSymbolAddress((void**)&p_seq2, g_seq2);
    cudaGetSymbolAddress((void**)&p_f2, g_feats2);
    cudaGetSymbolAddress((void**)&p_xp2, g_xp2);
    cudaGetSymbolAddress((void**)&p_WT2, g_WT2);
    cudaGetSymbolAddress((void**)&p_y2, g_y2);
    cudaGetSymbolAddress((void**)&p_ss2, g_sstat2);

    Seg seg1, seg2; int L1, L2;
    make_segs(Tt, S1n, seg1, L1);
    make_segs(S1n, S2n, seg2, L2);

    // recurrent weight transposes
    k_transpose<<<(4 * C1 * C1 + 255) / 256, 256>>>(Whh1, p_WT1, 4 * C1, C1);
    k_transpose<<<(4 * C2 * C2 + 255) / 256, 256>>>(Whh2, p_WT2, 4 * C2, C2);

    // ---- data BN ----
    k_bn0_stats<<<150, 256>>>(x, p_stat0);
    k_bn0_apply<<<(NM * Tt * Vv * Cin + 255) / 256, 256>>>(x, p_stat0, dbn_g, dbn_b, p_h0);

    // ---- GCN 1 ----
    k_gcn_support<<<NM * Tt, 256, Vv * Cin * sizeof(float)>>>(p_h0, Ap1, Ar1, p_S1, Tt, Cin);
    {
        dim3 grid((C1 + TBN - 1) / TBN, (NM * Tt * Vv + TBM - 1) / TBM);
        k_gemm_abt<<<grid, 256>>>(p_S1, W1, b1, nullptr, p_O1, NM * Tt * Vv, C1, Kk * Cin);
    }
    k_colstats<<<C1, 256>>>(p_O1, p_stat1, NM * Tt * Vv, C1);
    k_bn_relu_seq<<<(NM * Tt * Vv * C1 + 255) / 256, 256>>>(p_O1, p_stat1, bn1_g, bn1_b, p_seq1, Tt, C1, NM * Tt * Vv * C1);

    // ---- logsig + LSTM 1 ----
    k_feats<<<100 * S1n, 256>>>(p_seq1, p_f1, Tt, C1, S1n, L1, IN1, seg1);
    {
        dim3 grid((4 * C1 + TBN - 1) / TBN, (100 * S1n + TBM - 1) / TBM);
        k_gemm_abt<<<grid, 256>>>(p_f1, Wih1, bih1, bhh1, p_xp1, 100 * S1n, 4 * C1, IN1);
    }
    int smem1 = (6 * C1 + C1 * 4 * C1) * (int)sizeof(float);
    cudaFuncSetAttribute(k_lstm, cudaFuncAttributeMaxDynamicSharedMemorySize, smem1);
    k_lstm<<<100, 4 * C1, smem1>>>(p_xp1, p_WT1, p_y1, S1n, C1, 1);
    k_seg_stats<<<S1n, 256>>>(p_y1, p_ss1, S1n, C1);
    k_seg_apply<<<(NM * S1n * Vv * C1 + 255) / 256, 256>>>(p_y1, p_ss1, bs1_g, bs1_b, p_h1b, S1n, C1, NM * S1n * Vv * C1);

    // ---- GCN 2 ----
    k_gcn_support<<<NM * S1n, 256, Vv * C1 * sizeof(float)>>>(p_h1b, Ap2, Ar2, p_S2, S1n, C1);
    {
        dim3 grid((C2 + TBN - 1) / TBN, (NM * S1n * Vv + TBM - 1) / TBM);
        k_gemm_abt<<<grid, 256>>>(p_S2, W2, b2, nullptr, p_O2, NM * S1n * Vv, C2, Kk * C1);
    }
    k_colstats<<<C2, 256>>>(p_O2, p_stat2, NM * S1n * Vv, C2);
    k_bn_relu_seq<<<(NM * S1n * Vv * C2 + 255) / 256, 256>>>(p_O2, p_stat2, bn2_g, bn2_b, p_seq2, S1n, C2, NM * S1n * Vv * C2);

    // ---- logsig + LSTM 2 ----
    k_feats<<<100 * S2n, 256>>>(p_seq2, p_f2, S1n, C2, S2n, L2, IN2, seg2);
    {
        dim3 grid((4 * C2 + TBN - 1) / TBN, (100 * S2n + TBM - 1) / TBM);
        k_gemm_abt<<<grid, 256>>>(p_f2, Wih2, bih2, bhh2, p_xp2, 100 * S2n, 4 * C2, IN2);
    }
    int smem2 = 6 * C2 * (int)sizeof(float);
    k_lstm<<<100, 4 * C2, smem2>>>(p_xp2, p_WT2, p_y2, S2n, C2, 0);
    k_seg_stats<<<S2n, 256>>>(p_y2, p_ss2, S2n, C2);

    // ---- pooling + fc ----
    k_final<<<Nn, 256>>>(p_y2, p_ss2, bs2_g, bs2_b, fcW, fcb, out);
}

// round 2
// speedup vs baseline: 2.3263x; 2.3263x over previous
#include <cuda_runtime.h>
#include <cuda_bf16.h>
#include <cmath>
#include <cstdint>

// ======================= model constants =======================
#define Nn    2
#define Mm_   2
#define NM    4
#define Cin   3
#define Tt    100
#define Vv    25
#define Kk    13
#define C1    96
#define C2    192
#define S1n   50
#define S2n   30
#define IN1   4752     // 2*96 + 4560
#define IN2   18720    // 2*192 + 18336
#define KP1   4768     // IN1 padded to /32
#define KG2   1248     // 13*96
#define NCLS  60

struct Seg { int starts[64]; int ends[64]; };

// ======================= device scratch ========================
__device__ float g_h0[NM*Tt*Vv*Cin];
__device__ float g_stat0[150*2];
__device__ float g_S1[NM*Tt*Vv*Kk*Cin];
__device__ float g_O1[NM*Tt*Vv*C1];
__device__ float g_stat1[C1*2];
__device__ float g_seq1[100*Tt*C1];
__device__ float g_xp1[5000*4*C1];
__device__ float g_WT1[C1*4*C1];
__device__ float g_y1[100*S1n*C1];
__device__ float g_sstat1[S1n*2];
__device__ float g_h1b[NM*S1n*Vv*C1];
__device__ float g_O2[NM*S1n*Vv*C2];
__device__ float g_stat2[C2*2];
__device__ float g_seq2[100*S1n*C2];
__device__ float g_xp2[3000*4*C2];
__device__ float g_WT2[C2*4*C2];
__device__ float g_y2[100*S2n*C2];
__device__ float g_sstat2[S2n*2];

// bf16 hi/lo split operands for tensor-core GEMMs
__device__ __nv_bfloat16 g_f1hi[5000*KP1],  g_f1lo[5000*KP1];
__device__ __nv_bfloat16 g_f2hi[3000*IN2],  g_f2lo[3000*IN2];
__device__ __nv_bfloat16 g_Wih1hi[384*KP1], g_Wih1lo[384*KP1];
__device__ __nv_bfloat16 g_Wih2hi[768*IN2], g_Wih2lo[768*IN2];
__device__ __nv_bfloat16 g_W2hi[192*KG2],   g_W2lo[192*KG2];
__device__ __nv_bfloat16 g_S2hi[5000*KG2],  g_S2lo[5000*KG2];

// ======================= helpers ===============================

__device__ __forceinline__ void st_split(__nv_bfloat16* hi, __nv_bfloat16* lo, size_t i, float v) {
    __nv_bfloat16 h = __float2bfloat16(v);
    hi[i] = h;
    lo[i] = __float2bfloat16(v - __bfloat162float(h));
}

__device__ __forceinline__ void cp_async16(void* smem, const void* gmem) {
    uint32_t s = (uint32_t)__cvta_generic_to_shared(smem);
    asm volatile("cp.async.cg.shared.global [%0], [%1], 16;\n" :: "r"(s), "l"(gmem));
}
#define CP_COMMIT() asm volatile("cp.async.commit_group;\n" ::: "memory")
#define CP_WAIT1()  asm volatile("cp.async.wait_group 1;\n" ::: "memory")

__device__ __forceinline__ void mma16816(float* d, const uint32_t* a, const uint32_t* b) {
    asm volatile(
        "mma.sync.aligned.m16n8k16.row.col.f32.bf16.bf16.f32 "
        "{%0,%1,%2,%3}, {%4,%5,%6,%7}, {%8,%9}, {%0,%1,%2,%3};"
        : "+f"(d[0]), "+f"(d[1]), "+f"(d[2]), "+f"(d[3])
        : "r"(a[0]), "r"(a[1]), "r"(a[2]), "r"(a[3]), "r"(b[0]), "r"(b[1]));
}

// ======================= kernels ===============================

__global__ void k_transpose(const float* __restrict__ W, float* __restrict__ WT, int G, int H) {
    int idx = blockIdx.x * blockDim.x + threadIdx.x;
    if (idx < G * H) {
        int j = idx / H, k = idx % H;
        WT[k * G + j] = W[j * H + k];
    }
}

// fp32 (N,K) -> bf16 hi/lo (N,Kpad) with zero tail
__global__ void k_cvt_pad(const float* __restrict__ W, __nv_bfloat16* __restrict__ hi,
                          __nv_bfloat16* __restrict__ lo, int Nrows, int K, int Kpad) {
    int idx = blockIdx.x * blockDim.x + threadIdx.x;
    if (idx >= Nrows * Kpad) return;
    int n = idx / Kpad, k = idx % Kpad;
    float v = (k < K) ? W[(size_t)n * K + k] : 0.f;
    st_split(hi, lo, idx, v);
}

__global__ void k_bn0_stats(const float* __restrict__ x, float* __restrict__ stat) {
    int ch = blockIdx.x;
    int m = ch / (Vv * Cin);
    int v = (ch / Cin) % Vv;
    int c = ch % Cin;
    double s = 0.0, ss = 0.0;
    for (int i = threadIdx.x; i < Nn * Tt; i += blockDim.x) {
        int n = i / Tt, t = i % Tt;
        float val = x[(((n * Cin + c) * Tt + t) * Vv + v) * Mm_ + m];
        s += val; ss += (double)val * val;
    }
    __shared__ double r1[256], r2[256];
    r1[threadIdx.x] = s; r2[threadIdx.x] = ss;
    __syncthreads();
    for (int off = 128; off > 0; off >>= 1) {
        if (threadIdx.x < off) { r1[threadIdx.x] += r1[threadIdx.x + off]; r2[threadIdx.x] += r2[threadIdx.x + off]; }
        __syncthreads();
    }
    if (threadIdx.x == 0) {
        double cnt = (double)(Nn * Tt);
        double mean = r1[0] / cnt;
        double var = r2[0] / cnt - mean * mean;
        if (var < 0.0) var = 0.0;
        stat[2 * ch] = (float)mean;
        stat[2 * ch + 1] = (float)(1.0 / sqrt(var + 1e-5));
    }
}

__global__ void k_bn0_apply(const float* __restrict__ x, const float* __restrict__ stat,
                            const float* __restrict__ g, const float* __restrict__ b,
                            float* __restrict__ h0) {
    int idx = blockIdx.x * blockDim.x + threadIdx.x;
    if (idx >= NM * Tt * Vv * Cin) return;
    int c = idx % Cin;
    int v = (idx / Cin) % Vv;
    int t = (idx / (Cin * Vv)) % Tt;
    int nm = idx / (Cin * Vv * Tt);
    int n = nm >> 1, m = nm & 1;
    int ch = m * (Vv * Cin) + v * Cin + c;
    float val = x[(((n * Cin + c) * Tt + t) * Vv + v) * Mm_ + m];
    h0[idx] = (val - stat[2 * ch]) * stat[2 * ch + 1] * g[ch] + b[ch];
}

// fp32 support (layer 1)
__global__ void k_gcn_support(const float* __restrict__ hin, const float* __restrict__ Ap,
                              const float* __restrict__ Ares, float* __restrict__ Sout,
                              int T, int Cc) {
    __shared__ float Asm[325 * 25];
    extern __shared__ float hsm[];
    int blk = blockIdx.x;
    for (int i = threadIdx.x; i < 325 * 25; i += blockDim.x) Asm[i] = Ap[i] + Ares[i];
    const float* hrow = hin + (size_t)blk * Vv * Cc;
    for (int i = threadIdx.x; i < Vv * Cc; i += blockDim.x) hsm[i] = hrow[i];
    __syncthreads();
    int tot = Vv * Kk * Cc;
    float* outrow = Sout + (size_t)blk * tot;
    for (int f = threadIdx.x; f < tot; f += blockDim.x) {
        int c = f % Cc;
        int k = (f / Cc) % Kk;
        int v = f / (Kk * Cc);
        const float* arow = Asm + (k * Vv + v) * Vv;
        float acc = 0.f;
        #pragma unroll
        for (int u = 0; u < Vv; u++) acc += arow[u] * hsm[u * Cc + c];
        outrow[f] = acc;
    }
}

// bf16 hi/lo support (layer 2)
__global__ void k_gcn_support_bf(const float* __restrict__ hin, const float* __restrict__ Ap,
                                 const float* __restrict__ Ares, __nv_bfloat16* __restrict__ Shi,
                                 __nv_bfloat16* __restrict__ Slo, int T, int Cc) {
    __shared__ float Asm[325 * 25];
    extern __shared__ float hsm[];
    int blk = blockIdx.x;
    for (int i = threadIdx.x; i < 325 * 25; i += blockDim.x) Asm[i] = Ap[i] + Ares[i];
    const float* hrow = hin + (size_t)blk * Vv * Cc;
    for (int i = threadIdx.x; i < Vv * Cc; i += blockDim.x) hsm[i] = hrow[i];
    __syncthreads();
    int tot = Vv * Kk * Cc;
    size_t base = (size_t)blk * tot;
    for (int f = threadIdx.x; f < tot; f += blockDim.x) {
        int c = f % Cc;
        int k = (f / Cc) % Kk;
        int v = f / (Kk * Cc);
        const float* arow = Asm + (k * Vv + v) * Vv;
        float acc = 0.f;
        #pragma unroll
        for (int u = 0; u < Vv; u++) acc += arow[u] * hsm[u * Cc + c];
        st_split(Shi, Slo, base + f, acc);
    }
}

// legacy fp32 GEMM (only gcn1 now): C = A*B^T + biases
#define TBM 64
#define TBN 64
#define TBK 16
__global__ void k_gemm_abt(const float* __restrict__ A, const float* __restrict__ B,
                           const float* __restrict__ bias1, const float* __restrict__ bias2,
                           float* __restrict__ C, int M, int N, int K) {
    __shared__ float As[TBK][TBM];
    __shared__ float Bs[TBK][TBN];
    int m0 = blockIdx.y * TBM;
    int n0 = blockIdx.x * TBN;
    int tid = threadIdx.x;
    int tx = tid & 15, ty = tid >> 4;
    float acc[4][4] = {};
    for (int kt = 0; kt < K; kt += TBK) {
        #pragma unroll
        for (int e = 0; e < 4; e++) {
            int idx = tid + e * 256;
            int r = idx >> 4, c = idx & 15;
            int gk = kt + c;
            int gm = m0 + r;
            As[c][r] = (gm < M && gk < K) ? A[(size_t)gm * K + gk] : 0.f;
            int gn = n0 + r;
            Bs[c][r] = (gn < N && gk < K) ? B[(size_t)gn * K + gk] : 0.f;
        }
        __syncthreads();
        #pragma unroll
        for (int kk = 0; kk < TBK; kk++) {
            float4 a4 = *reinterpret_cast<const float4*>(&As[kk][ty * 4]);
            float4 b4 = *reinterpret_cast<const float4*>(&Bs[kk][tx * 4]);
            float av[4] = {a4.x, a4.y, a4.z, a4.w};
            float bv[4] = {b4.x, b4.y, b4.z, b4.w};
            #pragma unroll
            for (int r = 0; r < 4; r++)
                #pragma unroll
                for (int c = 0; c < 4; c++) acc[r][c] += av[r] * bv[c];
        }
        __syncthreads();
    }
    #pragma unroll
    for (int r = 0; r < 4; r++) {
        int gm = m0 + ty * 4 + r;
        if (gm >= M) continue;
        #pragma unroll
        for (int c = 0; c < 4; c++) {
            int gn = n0 + tx * 4 + c;
            if (gn >= N) continue;
            float bv = (bias1 ? bias1[gn] : 0.f) + (bias2 ? bias2[gn] : 0.f);
            C[(size_t)gm * N + gn] = acc[r][c] + bv;
        }
    }
}

// =========== tensor-core GEMM: C[M,N] = A[M,K]*B[N,K]^T (bf16 hi/lo x3, fp32 acc) ===========
// K % 32 == 0, N % 64 == 0. 128 threads, 64x64 block tile, 32x32 warp tile.
__global__ void __launch_bounds__(128) k_mma_gemm(
    const __nv_bfloat16* __restrict__ Ahi, const __nv_bfloat16* __restrict__ Alo,
    const __nv_bfloat16* __restrict__ Bhi, const __nv_bfloat16* __restrict__ Blo,
    const float* __restrict__ bias1, const float* __restrict__ bias2,
    float* __restrict__ C, int M, int N, int K)
{
    __shared__ __nv_bfloat16 sA[2][2][64][40];   // [stage][hi/lo][row][k] pad 40 for banks+align
    __shared__ __nv_bfloat16 sB[2][2][64][40];
    const int m0 = blockIdx.y * 64, n0 = blockIdx.x * 64;
    const int tid = threadIdx.x;
    const int lane = tid & 31, warp = tid >> 5;
    const int wm = (warp & 1) * 32, wn = (warp >> 1) * 32;
    const int r = lane >> 2, s2 = (lane & 3) * 2;
    float acc[2][4][4];
    #pragma unroll
    for (int a = 0; a < 2; a++)
        #pragma unroll
        for (int b = 0; b < 4; b++)
            #pragma unroll
            for (int c = 0; c < 4; c++) acc[a][b][c] = 0.f;

    const int srow = tid >> 2;          // 0..31
    const int schk = (tid & 3) * 8;     // bf16 offset of this thread's 16B chunk
    const int nk = K >> 5;

    // prologue: stage chunk 0
    #pragma unroll
    for (int h = 0; h < 2; h++) {
        int row = srow + h * 32;
        int ga = m0 + row; if (ga >= M) ga = M - 1;
        int gb = n0 + row;
        cp_async16(&sA[0][0][row][schk], Ahi + (size_t)ga * K + schk);
        cp_async16(&sA[0][1][row][schk], Alo + (size_t)ga * K + schk);
        cp_async16(&sB[0][0][row][schk], Bhi + (size_t)gb * K + schk);
        cp_async16(&sB[0][1][row][schk], Blo + (size_t)gb * K + schk);
    }
    CP_COMMIT();

    for (int kc = 0; kc < nk; kc++) {
        int st = kc & 1;
        if (kc + 1 < nk) {
            int kt = (kc + 1) << 5;
            int sn = st ^ 1;
            #pragma unroll
            for (int h = 0; h < 2; h++) {
                int row = srow + h * 32;
                int ga = m0 + row; if (ga >= M) ga = M - 1;
                int gb = n0 + row;
                cp_async16(&sA[sn][0][row][schk], Ahi + (size_t)ga * K + kt + schk);
                cp_async16(&sA[sn][1][row][schk], Alo + (size_t)ga * K + kt + schk);
                cp_async16(&sB[sn][0][row][schk], Bhi + (size_t)gb * K + kt + schk);
                cp_async16(&sB[sn][1][row][schk], Blo + (size_t)gb * K + kt + schk);
            }
        }
        CP_COMMIT();
        CP_WAIT1();
        __syncthreads();

        #pragma unroll
        for (int ks = 0; ks < 2; ks++) {
            const int kb = ks * 16 + s2;
            uint32_t ah[2][4], al[2][4];
            #pragma unroll
            for (int mt = 0; mt < 2; mt++) {
                int row = wm + mt * 16 + r;
                const __nv_bfloat16* p0 = &sA[st][0][row][kb];
                const __nv_bfloat16* p1 = &sA[st][0][row + 8][kb];
                ah[mt][0] = *(const uint32_t*)p0;
                ah[mt][1] = *(const uint32_t*)p1;
                ah[mt][2] = *(const uint32_t*)(p0 + 8);
                ah[mt][3] = *(const uint32_t*)(p1 + 8);
                const __nv_bfloat16* q0 = &sA[st][1][row][kb];
                const __nv_bfloat16* q1 = &sA[st][1][row + 8][kb];
                al[mt][0] = *(const uint32_t*)q0;
                al[mt][1] = *(const uint32_t*)q1;
                al[mt][2] = *(const uint32_t*)(q0 + 8);
                al[mt][3] = *(const uint32_t*)(q1 + 8);
            }
            #pragma unroll
            for (int nt = 0; nt < 4; nt++) {
                int nrow = wn + nt * 8 + r;
                uint32_t bh[2], bl[2];
                const __nv_bfloat16* p = &sB[st][0][nrow][kb];
                bh[0] = *(const uint32_t*)p;
                bh[1] = *(const uint32_t*)(p + 8);
                const __nv_bfloat16* q = &sB[st][1][nrow][kb];
                bl[0] = *(const uint32_t*)q;
                bl[1] = *(const uint32_t*)(q + 8);
                #pragma unroll
                for (int mt = 0; mt < 2; mt++) {
                    mma16816(acc[mt][nt], ah[mt], bh);
                    mma16816(acc[mt][nt], ah[mt], bl);
                    mma16816(acc[mt][nt], al[mt], bh);
                }
            }
        }
        __syncthreads();
    }

    #pragma unroll
    for (int mt = 0; mt < 2; mt++) {
        int gm = m0 + wm + mt * 16 + r;
        #pragma unroll
        for (int nt = 0; nt < 4; nt++) {
            int gn = n0 + wn + nt * 8 + s2;
            float bv0 = 0.f, bv1 = 0.f;
            if (bias1) { bv0 += bias1[gn]; bv1 += bias1[gn + 1]; }
            if (bias2) { bv0 += bias2[gn]; bv1 += bias2[gn + 1]; }
            if (gm < M) {
                C[(size_t)gm * N + gn]     = acc[mt][nt][0] + bv0;
                C[(size_t)gm * N + gn + 1] = acc[mt][nt][1] + bv1;
            }
            if (gm + 8 < M) {
                C[(size_t)(gm + 8) * N + gn]     = acc[mt][nt][2] + bv0;
                C[(size_t)(gm + 8) * N + gn + 1] = acc[mt][nt][3] + bv1;
            }
        }
    }
}

__global__ void k_colstats(const float* __restrict__ X, float* __restrict__ stat, int Mrows, int Ncols) {
    int col = blockIdx.x;
    double s = 0.0, ss = 0.0;
    for (int rr = threadIdx.x; rr < Mrows; rr += blockDim.x) {
        float v = X[(size_t)rr * Ncols + col];
        s += v; ss += (double)v * v;
    }
    __shared__ double r1[256], r2[256];
    r1[threadIdx.x] = s; r2[threadIdx.x] = ss;
    __syncthreads();
    for (int off = 128; off > 0; off >>= 1) {
        if (threadIdx.x < off) { r1[threadIdx.x] += r1[threadIdx.x + off]; r2[threadIdx.x] += r2[threadIdx.x + off]; }
        __syncthreads();
    }
    if (threadIdx.x == 0) {
        double cnt = (double)Mrows;
        double mean = r1[0] / cnt;
        double var = r2[0] / cnt - mean * mean;
        if (var < 0.0) var = 0.0;
        stat[2 * col] = (float)mean;
        stat[2 * col + 1] = (float)(1.0 / sqrt(var + 1e-5));
    }
}

__global__ void k_bn_relu_seq(const float* __restrict__ O, const float* __restrict__ stat,
                              const float* __restrict__ g, const float* __restrict__ bb,
                              float* __restrict__ seq, int T, int Cc, int total) {
    int idx = blockIdx.x * blockDim.x + threadIdx.x;
    if (idx >= total) return;
    int c = idx % Cc;
    int j = idx / Cc;
    int v = j % Vv;
    int t = (j / Vv) % T;
    int nm = j / (Vv * T);
    float val = (O[idx] - stat[2 * c]) * stat[2 * c + 1] * g[c] + bb[c];
    val = fmaxf(val, 0.f);
    int b = nm * Vv + v;
    seq[((size_t)b * T + t) * Cc + c] = val;
}

// log-sig feats -> bf16 hi/lo (Kpad stride, zero tail)
__global__ void k_feats_bf(const float* __restrict__ seq, __nv_bfloat16* __restrict__ fhi,
                           __nv_bfloat16* __restrict__ flo,
                           int T, int d, int S, int L, int in_dim, int Kpad, Seg seg) {
    __shared__ float s_pts[4][192];
    __shared__ float s_rel[3][192];
    __shared__ float s_dx[3][192];
    int bs = blockIdx.x;
    int b = bs / S, s = bs % S;
    const float* xb = seq + (size_t)b * T * d;
    for (int l = 0; l < L; l++) {
        int idx = seg.starts[s] + l;
        if (idx > seg.ends[s]) idx = seg.ends[s];
        for (int i = threadIdx.x; i < d; i += blockDim.x) s_pts[l][i] = xb[(size_t)idx * d + i];
    }
    __syncthreads();
    __nv_bfloat16* ohi = fhi + (size_t)bs * Kpad;
    __nv_bfloat16* olo = flo + (size_t)bs * Kpad;
    for (int i = threadIdx.x; i < d; i += blockDim.x) {
        float p0 = s_pts[0][i];
        for (int l = 0; l + 1 < L; l++) {
            s_rel[l][i] = s_pts[l][i] - p0;
            s_dx[l][i] = s_pts[l + 1][i] - s_pts[l][i];
        }
        st_split(ohi, olo, i, p0);
        st_split(ohi, olo, d + i, s_pts[L - 1][i] - p0);
    }
    __syncthreads();
    int Lm1 = L - 1;
    for (int i = threadIdx.x; i < d - 1; i += blockDim.x) {
        int base = 2 * d + i * (2 * d - i - 1) / 2;
        float ri[3], di[3];
        for (int l = 0; l < Lm1; l++) { ri[l] = s_rel[l][i]; di[l] = s_dx[l][i]; }
        for (int j = i + 1; j < d; j++) {
            float acc = 0.f;
            for (int l = 0; l < Lm1; l++) acc += ri[l] * s_dx[l][j] - s_rel[l][j] * di[l];
            st_split(ohi, olo, base + (j - i - 1), 0.5f * acc);
        }
    }
    __nv_bfloat16 z = __float2bfloat16(0.f);
    for (int i = in_dim + threadIdx.x; i < Kpad; i += blockDim.x) { ohi[i] = z; olo[i] = z; }
}

__device__ __forceinline__ float sigf(float x) { return 1.f / (1.f + expf(-x)); }

__global__ void k_lstm(const float* __restrict__ xp, const float* __restrict__ WT,
                       float* __restrict__ y, int S, int H, int stageW) {
    extern __shared__ float sm[];
    float* sh = sm;
    float* sc = sm + H;
    float* sg = sm + 2 * H;
    float* sW = sm + 6 * H;
    int b = blockIdx.x;
    int j = threadIdx.x;
    int G = 4 * H;
    if (stageW) {
        for (int idx = j; idx < H * G; idx += blockDim.x) sW[idx] = WT[idx];
    }
    if (j < H) { sh[j] = 0.f; sc[j] = 0.f; }
    __syncthreads();
    const float* W = stageW ? sW : WT;
    for (int s = 0; s < S; s++) {
        float g = xp[((size_t)b * S + s) * G + j];
        for (int k = 0; k < H; k++) g += sh[k] * W[k * G + j];
        sg[j] = g;
        __syncthreads();
        if (j < H) {
            float iv = sigf(sg[j]);
            float fv = sigf(sg[H + j]);
            float gv = tanhf(sg[2 * H + j]);
            float ov = sigf(sg[3 * H + j]);
            float cn = fv * sc[j] + iv * gv;
            sc[j] = cn;
            float hn = ov * tanhf(cn);
            sh[j] = hn;
            y[((size_t)b * S + s) * H + j] = hn;
        }
        __syncthreads();
    }
}

__global__ void k_seg_stats(const float* __restrict__ y, float* __restrict__ stat, int S, int H) {
    int s = blockIdx.x;
    double sum = 0.0, ssq = 0.0;
    for (int i = threadIdx.x; i < 100 * H; i += blockDim.x) {
        int b = i / H, h = i % H;
        float v = y[((size_t)b * S + s) * H + h];
        sum += v; ssq += (double)v * v;
    }
    __shared__ double r1[256], r2[256];
    r1[threadIdx.x] = sum; r2[threadIdx.x] = ssq;
    __syncthreads();
    for (int off = 128; off > 0; off >>= 1) {
        if (threadIdx.x < off) { r1[threadIdx.x] += r1[threadIdx.x + off]; r2[threadIdx.x] += r2[threadIdx.x + off]; }
        __syncthreads();
    }
    if (threadIdx.x == 0) {
        double cnt = 100.0 * H;
        double mean = r1[0] / cnt;
        double var = r2[0] / cnt - mean * mean;
        if (var < 0.0) var = 0.0;
        stat[2 * s] = (float)mean;
        stat[2 * s + 1] = (float)(1.0 / sqrt(var + 1e-5));
    }
}

__global__ void k_seg_apply(const float* __restrict__ y, const float* __restrict__ stat,
                            const float* __restrict__ g, const float* __restrict__ bb,
                            float* __restrict__ hout, int S, int H, int total) {
    int idx = blockIdx.x * blockDim.x + threadIdx.x;
    if (idx >= total) return;
    int c = idx % H;
    int rr = idx / H;
    int v = rr % Vv;
    int s = (rr / Vv) % S;
    int nm = rr / (Vv * S);
    int b = nm * Vv + v;
    float val = (y[((size_t)b * S + s) * H + c] - stat[2 * s]) * stat[2 * s + 1] * g[s] + bb[s];
    hout[idx] = val;
}

__global__ void k_final(const float* __restrict__ y2, const float* __restrict__ stat,
                        const float* __restrict__ g, const float* __restrict__ bb,
                        const float* __restrict__ fcW, const float* __restrict__ fcb,
                        float* __restrict__ out) {
    __shared__ float pooled[C2];
    int n = blockIdx.x;
    for (int o = threadIdx.x; o < C2; o += blockDim.x) {
        float acc = 0.f;
        for (int m = 0; m < 2; m++)
            for (int v = 0; v < Vv; v++) {
                int b = (n * 2 + m) * Vv + v;
                for (int s = 0; s < S2n; s++) {
                    float val = (y2[((size_t)b * S2n + s) * C2 + o] - stat[2 * s]) * stat[2 * s + 1] * g[s] + bb[s];
                    acc += val;
                }
            }
        pooled[o] = acc / (2.f * Vv * S2n);
    }
    __syncthreads();
    for (int cls = threadIdx.x; cls < NCLS; cls += blockDim.x) {
        float acc = fcb[cls];
        for (int o = 0; o < C2; o++) acc += pooled[o] * fcW[cls * C2 + o];
        out[n * NCLS + cls] = acc;
    }
}

// ======================= host =======================

static void make_segs(int T, int S, Seg& seg, int& L) {
    double delta = (double)(T - 1) / (double)S;
    int tv[65];
    for (int i = 0; i <= S; i++) {
        double v = 1.0 + delta * (double)i;
        tv[i] = (int)nearbyint(v);
    }
    tv[S] = T;
    L = 0;
    for (int s = 0; s < S; s++) {
        seg.starts[s] = tv[s] - 1;
        seg.ends[s] = tv[s + 1] - 1;
        int len = seg.ends[s] - seg.starts[s] + 1;
        if (len > L) L = len;
    }
    if (L > 4) L = 4;
}

extern "C" void kernel_launch(void* const* d_in, const int* in_sizes, int n_in,
                              void* d_out, int out_size) {
    (void)in_sizes; (void)n_in; (void)out_size;
    const float* x        = (const float*)d_in[0];
    const float* dbn_g    = (const float*)d_in[2];
    const float* dbn_b    = (const float*)d_in[3];
    const float* Ap1      = (const float*)d_in[4];
    const float* Ar1      = (const float*)d_in[5];
    const float* W1       = (const float*)d_in[6];
    const float* b1       = (const float*)d_in[7];
    const float* bn1_g    = (const float*)d_in[8];
    const float* bn1_b    = (const float*)d_in[9];
    const float* Wih1     = (const float*)d_in[10];
    const float* Whh1     = (const float*)d_in[11];
    const float* bih1     = (const float*)d_in[12];
    const float* bhh1     = (const float*)d_in[13];
    const float* bs1_g    = (const float*)d_in[14];
    const float* bs1_b    = (const float*)d_in[15];
    const float* Ap2      = (const float*)d_in[16];
    const float* Ar2      = (const float*)d_in[17];
    const float* W2       = (const float*)d_in[18];
    const float* b2       = (const float*)d_in[19];
    const float* bn2_g    = (const float*)d_in[20];
    const float* bn2_b    = (const float*)d_in[21];
    const float* Wih2     = (const float*)d_in[22];
    const float* Whh2     = (const float*)d_in[23];
    const float* bih2     = (const float*)d_in[24];
    const float* bhh2     = (const float*)d_in[25];
    const float* bs2_g    = (const float*)d_in[26];
    const float* bs2_b    = (const float*)d_in[27];
    const float* fcW      = (const float*)d_in[28];
    const float* fcb      = (const float*)d_in[29];
    float* out = (float*)d_out;

    float *p_h0, *p_stat0, *p_S1, *p_O1, *p_stat1, *p_seq1, *p_xp1, *p_WT1, *p_y1,
          *p_ss1, *p_h1b, *p_O2, *p_stat2, *p_seq2, *p_xp2, *p_WT2, *p_y2, *p_ss2;
    __nv_bfloat16 *p_f1hi, *p_f1lo, *p_f2hi, *p_f2lo, *p_W1ih_hi, *p_W1ih_lo,
                  *p_W2ih_hi, *p_W2ih_lo, *p_W2hi, *p_W2lo, *p_S2hi, *p_S2lo;
    cudaGetSymbolAddress((void**)&p_h0, g_h0);
    cudaGetSymbolAddress((void**)&p_stat0, g_stat0);
    cudaGetSymbolAddress((void**)&p_S1, g_S1);
    cudaGetSymbolAddress((void**)&p_O1, g_O1);
    cudaGetSymbolAddress((void**)&p_stat1, g_stat1);
    cudaGetSymbolAddress((void**)&p_seq1, g_seq1);
    cudaGetSymbolAddress((void**)&p_xp1, g_xp1);
    cudaGetSymbolAddress((void**)&p_WT1, g_WT1);
    cudaGetSymbolAddress((void**)&p_y1, g_y1);
    cudaGetSymbolAddress((void**)&p_ss1, g_sstat1);
    cudaGetSymbolAddress((void**)&p_h1b, g_h1b);
    cudaGetSymbolAddress((void**)&p_O2, g_O2);
    cudaGetSymbolAddress((void**)&p_stat2, g_stat2);
    cudaGetSymbolAddress((void**)&p_seq2, g_seq2);
    cudaGetSymbolAddress((void**)&p_xp2, g_xp2);
    cudaGetSymbolAddress((void**)&p_WT2, g_WT2);
    cudaGetSymbolAddress((void**)&p_y2, g_y2);
    cudaGetSymbolAddress((void**)&p_ss2, g_sstat2);
    cudaGetSymbolAddress((void**)&p_f1hi, g_f1hi);
    cudaGetSymbolAddress((void**)&p_f1lo, g_f1lo);
    cudaGetSymbolAddress((void**)&p_f2hi, g_f2hi);
    cudaGetSymbolAddress((void**)&p_f2lo, g_f2lo);
    cudaGetSymbolAddress((void**)&p_W1ih_hi, g_Wih1hi);
    cudaGetSymbolAddress((void**)&p_W1ih_lo, g_Wih1lo);
    cudaGetSymbolAddress((void**)&p_W2ih_hi, g_Wih2hi);
    cudaGetSymbolAddress((void**)&p_W2ih_lo, g_Wih2lo);
    cudaGetSymbolAddress((void**)&p_W2hi, g_W2hi);
    cudaGetSymbolAddress((void**)&p_W2lo, g_W2lo);
    cudaGetSymbolAddress((void**)&p_S2hi, g_S2hi);
    cudaGetSymbolAddress((void**)&p_S2lo, g_S2lo);

    Seg seg1, seg2; int L1, L2;
    make_segs(Tt, S1n, seg1, L1);
    make_segs(S1n, S2n, seg2, L2);

    // weight prep (transposes + bf16 hi/lo splits)
    k_transpose<<<(4 * C1 * C1 + 255) / 256, 256>>>(Whh1, p_WT1, 4 * C1, C1);
    k_transpose<<<(4 * C2 * C2 + 255) / 256, 256>>>(Whh2, p_WT2, 4 * C2, C2);
    k_cvt_pad<<<(384 * KP1 + 255) / 256, 256>>>(Wih1, p_W1ih_hi, p_W1ih_lo, 384, IN1, KP1);
    k_cvt_pad<<<(768 * IN2 + 255) / 256, 256>>>(Wih2, p_W2ih_hi, p_W2ih_lo, 768, IN2, IN2);
    k_cvt_pad<<<(192 * KG2 + 255) / 256, 256>>>(W2, p_W2hi, p_W2lo, 192, KG2, KG2);

    // ---- data BN ----
    k_bn0_stats<<<150, 256>>>(x, p_stat0);
    k_bn0_apply<<<(NM * Tt * Vv * Cin + 255) / 256, 256>>>(x, p_stat0, dbn_g, dbn_b, p_h0);

    // ---- GCN 1 (tiny, fp32 path) ----
    k_gcn_support<<<NM * Tt, 256, Vv * Cin * sizeof(float)>>>(p_h0, Ap1, Ar1, p_S1, Tt, Cin);
    {
        dim3 grid((C1 + TBN - 1) / TBN, (NM * Tt * Vv + TBM - 1) / TBM);
        k_gemm_abt<<<grid, 256>>>(p_S1, W1, b1, nullptr, p_O1, NM * Tt * Vv, C1, Kk * Cin);
    }
    k_colstats<<<C1, 256>>>(p_O1, p_stat1, NM * Tt * Vv, C1);
    k_bn_relu_seq<<<(NM * Tt * Vv * C1 + 255) / 256, 256>>>(p_O1, p_stat1, bn1_g, bn1_b, p_seq1, Tt, C1, NM * Tt * Vv * C1);

    // ---- logsig + LSTM 1 ----
    k_feats_bf<<<100 * S1n, 256>>>(p_seq1, p_f1hi, p_f1lo, Tt, C1, S1n, L1, IN1, KP1, seg1);
    {
        dim3 grid(384 / 64, (5000 + 63) / 64);
        k_mma_gemm<<<grid, 128>>>(p_f1hi, p_f1lo, p_W1ih_hi, p_W1ih_lo, bih1, bhh1, p_xp1, 5000, 384, KP1);
    }
    int smem1 = (6 * C1 + C1 * 4 * C1) * (int)sizeof(float);
    cudaFuncSetAttribute(k_lstm, cudaFuncAttributeMaxDynamicSharedMemorySize, smem1);
    k_lstm<<<100, 4 * C1, smem1>>>(p_xp1, p_WT1, p_y1, S1n, C1, 1);
    k_seg_stats<<<S1n, 256>>>(p_y1, p_ss1, S1n, C1);
    k_seg_apply<<<(NM * S1n * Vv * C1 + 255) / 256, 256>>>(p_y1, p_ss1, bs1_g, bs1_b, p_h1b, S1n, C1, NM * S1n * Vv * C1);

    // ---- GCN 2 (tensor path) ----
    k_gcn_support_bf<<<NM * S1n, 256, Vv * C1 * sizeof(float)>>>(p_h1b, Ap2, Ar2, p_S2hi, p_S2lo, S1n, C1);
    {
        dim3 grid(192 / 64, (5000 + 63) / 64);
        k_mma_gemm<<<grid, 128>>>(p_S2hi, p_S2lo, p_W2hi, p_W2lo, b2, nullptr, p_O2, 5000, 192, KG2);
    }
    k_colstats<<<C2, 256>>>(p_O2, p_stat2, NM * S1n * Vv, C2);
    k_bn_relu_seq<<<(NM * S1n * Vv * C2 + 255) / 256, 256>>>(p_O2, p_stat2, bn2_g, bn2_b, p_seq2, S1n, C2, NM * S1n * Vv * C2);

    // ---- logsig + LSTM 2 ----
    k_feats_bf<<<100 * S2n, 256>>>(p_seq2, p_f2hi, p_f2lo, S1n, C2, S2n, L2, IN2, IN2, seg2);
    {
        dim3 grid(768 / 64, (3000 + 63) / 64);
        k_mma_gemm<<<grid, 128>>>(p_f2hi, p_f2lo, p_W2ih_hi, p_W2ih_lo, bih2, bhh2, p_xp2, 3000, 768, IN2);
    }
    int smem2 = 6 * C2 * (int)sizeof(float);
    k_lstm<<<100, 4 * C2, smem2>>>(p_xp2, p_WT2, p_y2, S2n, C2, 0);
    k_seg_stats<<<S2n, 256>>>(p_y2, p_ss2, S2n, C2);

    // ---- pooling + fc ----
    k_final<<<Nn, 256>>>(p_y2, p_ss2, bs2_g, bs2_b, fcW, fcb, out);
}

// round 3
// speedup vs baseline: 3.7698x; 1.6205x over previous
#include <cuda_runtime.h>
#include <cuda_bf16.h>
#include <cuda_fp16.h>
#include <cmath>
#include <cstdint>

// ======================= model constants =======================
#define Nn    2
#define Mm_   2
#define NM    4
#define Cin   3
#define Tt    100
#define Vv    25
#define Kk    13
#define C1    96
#define C2    192
#define S1n   50
#define S2n   30
#define IN1   4752     // 2*96 + 4560
#define IN2   18720    // 2*192 + 18336
#define KP1   4768     // IN1 padded to /32
#define KG2   1248     // 13*96
#define NCLS  60

struct Seg { int starts[64]; int ends[64]; };

// ======================= device scratch ========================
__device__ float g_h0[NM*Tt*Vv*Cin];
__device__ float g_stat0[150*2];
__device__ float g_S1[NM*Tt*Vv*Kk*Cin];
__device__ float g_O1[NM*Tt*Vv*C1];
__device__ float g_stat1[C1*2];
__device__ float g_seq1[100*Tt*C1];
__device__ float g_xp1[5000*4*C1];
__device__ float g_WT1[C1*4*C1];
__device__ float g_y1[100*S1n*C1];
__device__ float g_sstat1[S1n*2];
__device__ float g_h1b[NM*S1n*Vv*C1];
__device__ float g_O2[NM*S1n*Vv*C2];
__device__ float g_stat2[C2*2];
__device__ float g_seq2[100*S1n*C2];
__device__ float g_xp2[3000*4*C2];
__device__ float g_WT2[C2*4*C2];
__device__ float g_y2[100*S2n*C2];
__device__ float g_sstat2[S2n*2];

// f16 operands for the two big xp GEMMs (A single, B hi/lo)
__device__ __half g_f1h[5000*KP1];
__device__ __half g_f2h[3000*IN2];
__device__ __half g_W1h_hi[384*KP1], g_W1h_lo[384*KP1];
__device__ __half g_W2ih_hi[768*IN2], g_W2ih_lo[768*IN2];

// bf16 hi/lo operands for gcn2 GEMM (3-pass, extra-safe)
__device__ __nv_bfloat16 g_W2hi[192*KG2],  g_W2lo[192*KG2];
__device__ __nv_bfloat16 g_S2hi[5000*KG2], g_S2lo[5000*KG2];

// ======================= helpers ===============================

__device__ __forceinline__ void st_split_bf(__nv_bfloat16* hi, __nv_bfloat16* lo, size_t i, float v) {
    __nv_bfloat16 h = __float2bfloat16(v);
    hi[i] = h;
    lo[i] = __float2bfloat16(v - __bfloat162float(h));
}

__device__ __forceinline__ void cp_async16(void* smem, const void* gmem) {
    uint32_t s = (uint32_t)__cvta_generic_to_shared(smem);
    asm volatile("cp.async.cg.shared.global [%0], [%1], 16;\n" :: "r"(s), "l"(gmem));
}
#define CP_COMMIT() asm volatile("cp.async.commit_group;\n" ::: "memory")
#define CP_WAIT1()  asm volatile("cp.async.wait_group 1;\n" ::: "memory")

__device__ __forceinline__ void mma16816_bf(float* d, const uint32_t* a, const uint32_t* b) {
    asm volatile(
        "mma.sync.aligned.m16n8k16.row.col.f32.bf16.bf16.f32 "
        "{%0,%1,%2,%3}, {%4,%5,%6,%7}, {%8,%9}, {%0,%1,%2,%3};"
        : "+f"(d[0]), "+f"(d[1]), "+f"(d[2]), "+f"(d[3])
        : "r"(a[0]), "r"(a[1]), "r"(a[2]), "r"(a[3]), "r"(b[0]), "r"(b[1]));
}

__device__ __forceinline__ void mma16816_f16(float* d, const uint32_t* a, uint32_t b0, uint32_t b1) {
    asm volatile(
        "mma.sync.aligned.m16n8k16.row.col.f32.f16.f16.f32 "
        "{%0,%1,%2,%3}, {%4,%5,%6,%7}, {%8,%9}, {%0,%1,%2,%3};"
        : "+f"(d[0]), "+f"(d[1]), "+f"(d[2]), "+f"(d[3])
        : "r"(a[0]), "r"(a[1]), "r"(a[2]), "r"(a[3]), "r"(b0), "r"(b1));
}

#define LDSM4(r0, r1, r2, r3, addr) \
    asm volatile("ldmatrix.sync.aligned.m8n8.x4.shared.b16 {%0,%1,%2,%3}, [%4];" \
        : "=r"(r0), "=r"(r1), "=r"(r2), "=r"(r3) : "r"(addr))

// ======================= small kernels =========================

__global__ void k_transpose(const float* __restrict__ W, float* __restrict__ WT, int G, int H) {
    int idx = blockIdx.x * blockDim.x + threadIdx.x;
    if (idx < G * H) {
        int j = idx / H, k = idx % H;
        WT[k * G + j] = W[j * H + k];
    }
}

// fp32 (N,K) -> f16 hi/lo (N,Kpad), zero tail
__global__ void k_cvt_f16split(const float* __restrict__ W, __half* __restrict__ hi,
                               __half* __restrict__ lo, int Nrows, int K, int Kpad) {
    int idx = blockIdx.x * blockDim.x + threadIdx.x;
    if (idx >= Nrows * Kpad) return;
    int n = idx / Kpad, k = idx % Kpad;
    float v = (k < K) ? W[(size_t)n * K + k] : 0.f;
    __half h = __float2half_rn(v);
    hi[idx] = h;
    lo[idx] = __float2half_rn(v - __half2float(h));
}

// fp32 (N,K) -> bf16 hi/lo
__global__ void k_cvt_bfsplit(const float* __restrict__ W, __nv_bfloat16* __restrict__ hi,
                              __nv_bfloat16* __restrict__ lo, int total) {
    int idx = blockIdx.x * blockDim.x + threadIdx.x;
    if (idx >= total) return;
    st_split_bf(hi, lo, idx, W[idx]);
}

__global__ void k_bn0_stats(const float* __restrict__ x, float* __restrict__ stat) {
    int ch = blockIdx.x;
    int m = ch / (Vv * Cin);
    int v = (ch / Cin) % Vv;
    int c = ch % Cin;
    double s = 0.0, ss = 0.0;
    for (int i = threadIdx.x; i < Nn * Tt; i += blockDim.x) {
        int n = i / Tt, t = i % Tt;
        float val = x[(((n * Cin + c) * Tt + t) * Vv + v) * Mm_ + m];
        s += val; ss += (double)val * val;
    }
    __shared__ double r1[256], r2[256];
    r1[threadIdx.x] = s; r2[threadIdx.x] = ss;
    __syncthreads();
    for (int off = 128; off > 0; off >>= 1) {
        if (threadIdx.x < off) { r1[threadIdx.x] += r1[threadIdx.x + off]; r2[threadIdx.x] += r2[threadIdx.x + off]; }
        __syncthreads();
    }
    if (threadIdx.x == 0) {
        double cnt = (double)(Nn * Tt);
        double mean = r1[0] / cnt;
        double var = r2[0] / cnt - mean * mean;
        if (var < 0.0) var = 0.0;
        stat[2 * ch] = (float)mean;
        stat[2 * ch + 1] = (float)(1.0 / sqrt(var + 1e-5));
    }
}

__global__ void k_bn0_apply(const float* __restrict__ x, const float* __restrict__ stat,
                            const float* __restrict__ g, const float* __restrict__ b,
                            float* __restrict__ h0) {
    int idx = blockIdx.x * blockDim.x + threadIdx.x;
    if (idx >= NM * Tt * Vv * Cin) return;
    int c = idx % Cin;
    int v = (idx / Cin) % Vv;
    int t = (idx / (Cin * Vv)) % Tt;
    int nm = idx / (Cin * Vv * Tt);
    int n = nm >> 1, m = nm & 1;
    int ch = m * (Vv * Cin) + v * Cin + c;
    float val = x[(((n * Cin + c) * Tt + t) * Vv + v) * Mm_ + m];
    h0[idx] = (val - stat[2 * ch]) * stat[2 * ch + 1] * g[ch] + b[ch];
}

// fp32 support (layer 1)
__global__ void k_gcn_support(const float* __restrict__ hin, const float* __restrict__ Ap,
                              const float* __restrict__ Ares, float* __restrict__ Sout,
                              int T, int Cc) {
    __shared__ float Asm[325 * 25];
    extern __shared__ float hsm[];
    int blk = blockIdx.x;
    for (int i = threadIdx.x; i < 325 * 25; i += blockDim.x) Asm[i] = Ap[i] + Ares[i];
    const float* hrow = hin + (size_t)blk * Vv * Cc;
    for (int i = threadIdx.x; i < Vv * Cc; i += blockDim.x) hsm[i] = hrow[i];
    __syncthreads();
    int tot = Vv * Kk * Cc;
    float* outrow = Sout + (size_t)blk * tot;
    for (int f = threadIdx.x; f < tot; f += blockDim.x) {
        int c = f % Cc;
        int k = (f / Cc) % Kk;
        int v = f / (Kk * Cc);
        const float* arow = Asm + (k * Vv + v) * Vv;
        float acc = 0.f;
        #pragma unroll
        for (int u = 0; u < Vv; u++) acc += arow[u] * hsm[u * Cc + c];
        outrow[f] = acc;
    }
}

// bf16 hi/lo support (layer 2)
__global__ void k_gcn_support_bf(const float* __restrict__ hin, const float* __restrict__ Ap,
                                 const float* __restrict__ Ares, __nv_bfloat16* __restrict__ Shi,
                                 __nv_bfloat16* __restrict__ Slo, int T, int Cc) {
    __shared__ float Asm[325 * 25];
    extern __shared__ float hsm[];
    int blk = blockIdx.x;
    for (int i = threadIdx.x; i < 325 * 25; i += blockDim.x) Asm[i] = Ap[i] + Ares[i];
    const float* hrow = hin + (size_t)blk * Vv * Cc;
    for (int i = threadIdx.x; i < Vv * Cc; i += blockDim.x) hsm[i] = hrow[i];
    __syncthreads();
    int tot = Vv * Kk * Cc;
    size_t base = (size_t)blk * tot;
    for (int f = threadIdx.x; f < tot; f += blockDim.x) {
        int c = f % Cc;
        int k = (f / Cc) % Kk;
        int v = f / (Kk * Cc);
        const float* arow = Asm + (k * Vv + v) * Vv;
        float acc = 0.f;
        #pragma unroll
        for (int u = 0; u < Vv; u++) acc += arow[u] * hsm[u * Cc + c];
        st_split_bf(Shi, Slo, base + f, acc);
    }
}

// fp32 GEMM (gcn1 only)
#define TBM 64
#define TBN 64
#define TBK 16
__global__ void k_gemm_abt(const float* __restrict__ A, const float* __restrict__ B,
                           const float* __restrict__ bias1,
                           float* __restrict__ C, int M, int N, int K) {
    __shared__ float As[TBK][TBM];
    __shared__ float Bs[TBK][TBN];
    int m0 = blockIdx.y * TBM;
    int n0 = blockIdx.x * TBN;
    int tid = threadIdx.x;
    int tx = tid & 15, ty = tid >> 4;
    float acc[4][4] = {};
    for (int kt = 0; kt < K; kt += TBK) {
        #pragma unroll
        for (int e = 0; e < 4; e++) {
            int idx = tid + e * 256;
            int r = idx >> 4, c = idx & 15;
            int gk = kt + c;
            int gm = m0 + r;
            As[c][r] = (gm < M && gk < K) ? A[(size_t)gm * K + gk] : 0.f;
            int gn = n0 + r;
            Bs[c][r] = (gn < N && gk < K) ? B[(size_t)gn * K + gk] : 0.f;
        }
        __syncthreads();
        #pragma unroll
        for (int kk = 0; kk < TBK; kk++) {
            float4 a4 = *reinterpret_cast<const float4*>(&As[kk][ty * 4]);
            float4 b4 = *reinterpret_cast<const float4*>(&Bs[kk][tx * 4]);
            float av[4] = {a4.x, a4.y, a4.z, a4.w};
            float bv[4] = {b4.x, b4.y, b4.z, b4.w};
            #pragma unroll
            for (int r = 0; r < 4; r++)
                #pragma unroll
                for (int c = 0; c < 4; c++) acc[r][c] += av[r] * bv[c];
        }
        __syncthreads();
    }
    #pragma unroll
    for (int r = 0; r < 4; r++) {
        int gm = m0 + ty * 4 + r;
        if (gm >= M) continue;
        #pragma unroll
        for (int c = 0; c < 4; c++) {
            int gn = n0 + tx * 4 + c;
            if (gn >= N) continue;
            C[(size_t)gm * N + gn] = acc[r][c] + (bias1 ? bias1[gn] : 0.f);
        }
    }
}

// ====== bf16 3-pass tensor GEMM (gcn2): 64x64 tile, 128 thr ======
__global__ void __launch_bounds__(128) k_mma_gemm_bf(
    const __nv_bfloat16* __restrict__ Ahi, const __nv_bfloat16* __restrict__ Alo,
    const __nv_bfloat16* __restrict__ Bhi, const __nv_bfloat16* __restrict__ Blo,
    const float* __restrict__ bias1,
    float* __restrict__ C, int M, int N, int K)
{
    __shared__ __nv_bfloat16 sA[2][2][64][40];
    __shared__ __nv_bfloat16 sB[2][2][64][40];
    const int m0 = blockIdx.y * 64, n0 = blockIdx.x * 64;
    const int tid = threadIdx.x;
    const int lane = tid & 31, warp = tid >> 5;
    const int wm = (warp & 1) * 32, wn = (warp >> 1) * 32;
    const int r = lane >> 2, s2 = (lane & 3) * 2;
    float acc[2][4][4];
    #pragma unroll
    for (int a = 0; a < 2; a++)
        #pragma unroll
        for (int b = 0; b < 4; b++)
            #pragma unroll
            for (int c = 0; c < 4; c++) acc[a][b][c] = 0.f;

    const int srow = tid >> 2;
    const int schk = (tid & 3) * 8;
    const int nk = K >> 5;

    #pragma unroll
    for (int h = 0; h < 2; h++) {
        int row = srow + h * 32;
        int ga = m0 + row; if (ga >= M) ga = M - 1;
        int gb = n0 + row; if (gb >= N) gb = N - 1;
        cp_async16(&sA[0][0][row][schk], Ahi + (size_t)ga * K + schk);
        cp_async16(&sA[0][1][row][schk], Alo + (size_t)ga * K + schk);
        cp_async16(&sB[0][0][row][schk], Bhi + (size_t)gb * K + schk);
        cp_async16(&sB[0][1][row][schk], Blo + (size_t)gb * K + schk);
    }
    CP_COMMIT();

    for (int kc = 0; kc < nk; kc++) {
        int st = kc & 1;
        if (kc + 1 < nk) {
            int kt = (kc + 1) << 5;
            int sn = st ^ 1;
            #pragma unroll
            for (int h = 0; h < 2; h++) {
                int row = srow + h * 32;
                int ga = m0 + row; if (ga >= M) ga = M - 1;
                int gb = n0 + row; if (gb >= N) gb = N - 1;
                cp_async16(&sA[sn][0][row][schk], Ahi + (size_t)ga * K + kt + schk);
                cp_async16(&sA[sn][1][row][schk], Alo + (size_t)ga * K + kt + schk);
                cp_async16(&sB[sn][0][row][schk], Bhi + (size_t)gb * K + kt + schk);
                cp_async16(&sB[sn][1][row][schk], Blo + (size_t)gb * K + kt + schk);
            }
        }
        CP_COMMIT();
        CP_WAIT1();
        __syncthreads();

        #pragma unroll
        for (int ks = 0; ks < 2; ks++) {
            const int kb = ks * 16 + s2;
            uint32_t ah[2][4], al[2][4];
            #pragma unroll
            for (int mt = 0; mt < 2; mt++) {
                int row = wm + mt * 16 + r;
                const __nv_bfloat16* p0 = &sA[st][0][row][kb];
                const __nv_bfloat16* p1 = &sA[st][0][row + 8][kb];
                ah[mt][0] = *(const uint32_t*)p0;
                ah[mt][1] = *(const uint32_t*)p1;
                ah[mt][2] = *(const uint32_t*)(p0 + 8);
                ah[mt][3] = *(const uint32_t*)(p1 + 8);
                const __nv_bfloat16* q0 = &sA[st][1][row][kb];
                const __nv_bfloat16* q1 = &sA[st][1][row + 8][kb];
                al[mt][0] = *(const uint32_t*)q0;
                al[mt][1] = *(const uint32_t*)q1;
                al[mt][2] = *(const uint32_t*)(q0 + 8);
                al[mt][3] = *(const uint32_t*)(q1 + 8);
            }
            #pragma unroll
            for (int nt = 0; nt < 4; nt++) {
                int nrow = wn + nt * 8 + r;
                uint32_t bh[2], bl[2];
                const __nv_bfloat16* p = &sB[st][0][nrow][kb];
                bh[0] = *(const uint32_t*)p;
                bh[1] = *(const uint32_t*)(p + 8);
                const __nv_bfloat16* q = &sB[st][1][nrow][kb];
                bl[0] = *(const uint32_t*)q;
                bl[1] = *(const uint32_t*)(q + 8);
                #pragma unroll
                for (int mt = 0; mt < 2; mt++) {
                    mma16816_bf(acc[mt][nt], ah[mt], bh);
                    mma16816_bf(acc[mt][nt], ah[mt], bl);
                    mma16816_bf(acc[mt][nt], al[mt], bh);
                }
            }
        }
        __syncthreads();
    }

    #pragma unroll
    for (int mt = 0; mt < 2; mt++) {
        int gm = m0 + wm + mt * 16 + r;
        #pragma unroll
        for (int nt = 0; nt < 4; nt++) {
            int gn = n0 + wn + nt * 8 + s2;
            if (gn >= N) continue;
            float bv0 = bias1 ? bias1[gn] : 0.f;
            float bv1 = bias1 ? bias1[gn + 1] : 0.f;
            if (gm < M) {
                C[(size_t)gm * N + gn]     = acc[mt][nt][0] + bv0;
                C[(size_t)gm * N + gn + 1] = acc[mt][nt][1] + bv1;
            }
            if (gm + 8 < M) {
                C[(size_t)(gm + 8) * N + gn]     = acc[mt][nt][2] + bv0;
                C[(size_t)(gm + 8) * N + gn + 1] = acc[mt][nt][3] + bv1;
            }
        }
    }
}

// ====== f16 2-pass tensor GEMM (xp1/xp2): 128x128 tile, 256 thr, ldmatrix, 3-stage ======
// C[M,N] = A[M,K] * (Bhi+Blo)[N,K]^T + bias1 + bias2.  K%32==0, N%128==0.
#define GF_STAGES 3
#define GF_LDA 40
__global__ void __launch_bounds__(256) k_gemm_f16(
    const __half* __restrict__ A,
    const __half* __restrict__ Bhi, const __half* __restrict__ Blo,
    const float* __restrict__ bias1, const float* __restrict__ bias2,
    float* __restrict__ C, int M, int N, int K)
{
    extern __shared__ __half smem[];
    __half* sA = smem;                              // [GF_STAGES][128][GF_LDA]
    __half* sB = smem + GF_STAGES * 128 * GF_LDA;   // [GF_STAGES][2][128][GF_LDA]

    const int m0 = blockIdx.y * 128, n0 = blockIdx.x * 128;
    const int tid = threadIdx.x;
    const int lane = tid & 31, warp = tid >> 5;
    const int wm = (warp & 1) * 64;        // 2 warps along M
    const int wn = (warp >> 1) * 32;       // 4 warps along N
    const int nk = K >> 5;

    const uint32_t sA_u = (uint32_t)__cvta_generic_to_shared(sA);
    const uint32_t sB_u = (uint32_t)__cvta_generic_to_shared(sB);

    // ldmatrix lane addressing
    const int lrow = lane & 15;
    const int lkh  = (lane >> 4) << 3;
    const int brow = ((lane >> 4) << 3) + (lane & 7);
    const int bkh  = ((lane >> 3) & 1) << 3;

    float acc[4][4][4];
    #pragma unroll
    for (int a = 0; a < 4; a++)
        #pragma unroll
        for (int b = 0; b < 4; b++)
            #pragma unroll
            for (int c = 0; c < 4; c++) acc[a][b][c] = 0.f;

    // --- async stage loader: stage slot st, k-offset kt ---
    auto load_stage = [&](int st, int kt) {
        // A: 128 rows x 32 halves = 512 x 16B chunks
        #pragma unroll
        for (int e = 0; e < 2; e++) {
            int i = tid + e * 256;
            int row = i >> 2, chk = (i & 3) << 3;
            int ga = m0 + row; if (ga >= M) ga = M - 1;
            cp_async16(&sA[(st * 128 + row) * GF_LDA + chk], A + (size_t)ga * K + kt + chk);
        }
        // Bhi/Blo: each 512 chunks
        #pragma unroll
        for (int e = 0; e < 2; e++) {
            int i = tid + e * 256;
            int row = i >> 2, chk = (i & 3) << 3;
            int gb = n0 + row; if (gb >= N) gb = N - 1;
            cp_async16(&sB[((st * 2 + 0) * 128 + row) * GF_LDA + chk], Bhi + (size_t)gb * K + kt + chk);
            cp_async16(&sB[((st * 2 + 1) * 128 + row) * GF_LDA + chk], Blo + (size_t)gb * K + kt + chk);
        }
    };

    load_stage(0, 0);
    CP_COMMIT();
    load_stage(1, 32);
    CP_COMMIT();

    for (int kc = 0; kc < nk; kc++) {
        int st = kc % GF_STAGES;
        CP_WAIT1();
        __syncthreads();
        if (kc + 2 < nk) {
            load_stage((kc + 2) % GF_STAGES, (kc + 2) << 5);
            CP_COMMIT();
        }

        #pragma unroll
        for (int ks = 0; ks < 2; ks++) {
            const int kb = ks * 16;
            uint32_t a[4][4];
            #pragma unroll
            for (int mt = 0; mt < 4; mt++) {
                uint32_t addr = sA_u + (((st * 128) + wm + mt * 16 + lrow) * GF_LDA + kb + lkh) * 2;
                LDSM4(a[mt][0], a[mt][1], a[mt][2], a[mt][3], addr);
            }
            #pragma unroll
            for (int g = 0; g < 2; g++) {
                uint32_t bh0, bh1, bh2, bh3, bl0, bl1, bl2, bl3;
                uint32_t addr_h = sB_u + ((((st * 2 + 0) * 128) + wn + g * 16 + brow) * GF_LDA + kb + bkh) * 2;
                uint32_t addr_l = sB_u + ((((st * 2 + 1) * 128) + wn + g * 16 + brow) * GF_LDA + kb + bkh) * 2;
                LDSM4(bh0, bh1, bh2, bh3, addr_h);
                LDSM4(bl0, bl1, bl2, bl3, addr_l);
                #pragma unroll
                for (int mt = 0; mt < 4; mt++) {
                    mma16816_f16(acc[mt][2 * g],     a[mt], bh0, bh1);
                    mma16816_f16(acc[mt][2 * g + 1], a[mt], bh2, bh3);
                    mma16816_f16(acc[mt][2 * g],     a[mt], bl0, bl1);
                    mma16816_f16(acc[mt][2 * g + 1], a[mt], bl2, bl3);
                }
            }
        }
        __syncthreads();
    }

    const int r = lane >> 2, cp = (lane & 3) * 2;
    #pragma unroll
    for (int mt = 0; mt < 4; mt++) {
        int gm = m0 + wm + mt * 16 + r;
        #pragma unroll
        for (int nt = 0; nt < 4; nt++) {
            int gn = n0 + wn + nt * 8 + cp;
            float bv0 = 0.f, bv1 = 0.f;
            if (bias1) { bv0 += bias1[gn]; bv1 += bias1[gn + 1]; }
            if (bias2) { bv0 += bias2[gn]; bv1 += bias2[gn + 1]; }
            if (gm < M) {
                C[(size_t)gm * N + gn]     = acc[mt][nt][0] + bv0;
                C[(size_t)gm * N + gn + 1] = acc[mt][nt][1] + bv1;
            }
            if (gm + 8 < M) {
                C[(size_t)(gm + 8) * N + gn]     = acc[mt][nt][2] + bv0;
                C[(size_t)(gm + 8) * N + gn + 1] = acc[mt][nt][3] + bv1;
            }
        }
    }
}

// ======================= elementwise chain =====================

__global__ void k_colstats(const float* __restrict__ X, float* __restrict__ stat, int Mrows, int Ncols) {
    int col = blockIdx.x;
    double s = 0.0, ss = 0.0;
    for (int rr = threadIdx.x; rr < Mrows; rr += blockDim.x) {
        float v = X[(size_t)rr * Ncols + col];
        s += v; ss += (double)v * v;
    }
    __shared__ double r1[256], r2[256];
    r1[threadIdx.x] = s; r2[threadIdx.x] = ss;
    __syncthreads();
    for (int off = 128; off > 0; off >>= 1) {
        if (threadIdx.x < off) { r1[threadIdx.x] += r1[threadIdx.x + off]; r2[threadIdx.x] += r2[threadIdx.x + off]; }
        __syncthreads();
    }
    if (threadIdx.x == 0) {
        double cnt = (double)Mrows;
        double mean = r1[0] / cnt;
        double var = r2[0] / cnt - mean * mean;
        if (var < 0.0) var = 0.0;
        stat[2 * col] = (float)mean;
        stat[2 * col + 1] = (float)(1.0 / sqrt(var + 1e-5));
    }
}

__global__ void k_bn_relu_seq(const float* __restrict__ O, const float* __restrict__ stat,
                              const float* __restrict__ g, const float* __restrict__ bb,
                              float* __restrict__ seq, int T, int Cc, int total) {
    int idx = blockIdx.x * blockDim.x + threadIdx.x;
    if (idx >= total) return;
    int c = idx % Cc;
    int j = idx / Cc;
    int v = j % Vv;
    int t = (j / Vv) % T;
    int nm = j / (Vv * T);
    float val = (O[idx] - stat[2 * c]) * stat[2 * c + 1] * g[c] + bb[c];
    val = fmaxf(val, 0.f);
    int b = nm * Vv + v;
    seq[((size_t)b * T + t) * Cc + c] = val;
}

// closed-form log-sig feats -> f16 (Kpad stride, zero tail)
// pts = [x[st], x[min(st+1,en)], x[min(st+2,en)]]; u = p1-p0, w = p2-p1
// feats = [p0, p2-p0, 0.5*(u_i w_j - u_j w_i) for i<j]
__global__ void k_feats_f16(const float* __restrict__ seq, __half* __restrict__ f,
                            int T, int d, int S, int in_dim, int Kpad, Seg seg) {
    __shared__ float s_su[192], s_w[192];
    int bs = blockIdx.x;
    int b = bs / S, s = bs % S;
    int st = seg.starts[s], en = seg.ends[s];
    int i1 = min(st + 1, en), i2 = min(st + 2, en);
    const float* x0 = seq + ((size_t)b * T + st) * d;
    const float* x1 = seq + ((size_t)b * T + i1) * d;
    const float* x2 = seq + ((size_t)b * T + i2) * d;
    __half* out = f + (size_t)bs * Kpad;
    for (int i = threadIdx.x; i < d; i += blockDim.x) {
        float p0 = x0[i], p1 = x1[i], p2 = x2[i];
        s_su[i] = 0.5f * (p1 - p0);
        s_w[i] = p2 - p1;
        out[i] = __float2half_rn(p0);
        out[d + i] = __float2half_rn(p2 - p0);
    }
    __syncthreads();
    if (en - st < 2) {
        // w == 0 -> all levy zero; vector zero-fill [2d, Kpad)
        __half2* o2 = (__half2*)(out + 2 * d);
        int n2 = (Kpad - 2 * d) >> 1;
        __half2 z = __floats2half2_rn(0.f, 0.f);
        for (int i = threadIdx.x; i < n2; i += blockDim.x) o2[i] = z;
        return;
    }
    for (int i = threadIdx.x; i < d - 1; i += blockDim.x) {
        float sui = s_su[i], wi = s_w[i];
        __half* op = out + 2 * d + i * (2 * d - i - 1) / 2 - (i + 1);
        for (int j = i + 1; j < d; j++) {
            float v = fmaf(sui, s_w[j], -(wi * s_su[j]));
            op[j] = __float2half_rn(v);
        }
    }
    for (int i = in_dim + threadIdx.x; i < Kpad; i += blockDim.x)
        out[i] = __float2half_rn(0.f);
}

__device__ __forceinline__ float sigf(float x) { return 1.f / (1.f + expf(-x)); }

__global__ void k_lstm(const float* __restrict__ xp, const float* __restrict__ WT,
                       float* __restrict__ y, int S, int H, int stageW) {
    extern __shared__ float sm[];
    float* sh = sm;
    float* sc = sm + H;
    float* sg = sm + 2 * H;
    float* sW = sm + 6 * H;
    int b = blockIdx.x;
    int j = threadIdx.x;
    int G = 4 * H;
    if (stageW) {
        for (int idx = j; idx < H * G; idx += blockDim.x) sW[idx] = WT[idx];
    }
    if (j < H) { sh[j] = 0.f; sc[j] = 0.f; }
    __syncthreads();
    const float* W = stageW ? sW : WT;
    for (int s = 0; s < S; s++) {
        float g = xp[((size_t)b * S + s) * G + j];
        for (int k = 0; k < H; k++) g += sh[k] * W[k * G + j];
        sg[j] = g;
        __syncthreads();
        if (j < H) {
            float iv = sigf(sg[j]);
            float fv = sigf(sg[H + j]);
            float gv = tanhf(sg[2 * H + j]);
            float ov = sigf(sg[3 * H + j]);
            float cn = fv * sc[j] + iv * gv;
            sc[j] = cn;
            float hn = ov * tanhf(cn);
            sh[j] = hn;
            y[((size_t)b * S + s) * H + j] = hn;
        }
        __syncthreads();
    }
}

__global__ void k_seg_stats(const float* __restrict__ y, float* __restrict__ stat, int S, int H) {
    int s = blockIdx.x;
    double sum = 0.0, ssq = 0.0;
    for (int i = threadIdx.x; i < 100 * H; i += blockDim.x) {
        int b = i / H, h = i % H;
        float v = y[((size_t)b * S + s) * H + h];
        sum += v; ssq += (double)v * v;
    }
    __shared__ double r1[256], r2[256];
    r1[threadIdx.x] = sum; r2[threadIdx.x] = ssq;
    __syncthreads();
    for (int off = 128; off > 0; off >>= 1) {
        if (threadIdx.x < off) { r1[threadIdx.x] += r1[threadIdx.x + off]; r2[threadIdx.x] += r2[threadIdx.x + off]; }
        __syncthreads();
    }
    if (threadIdx.x == 0) {
        double cnt = 100.0 * H;
        double mean = r1[0] / cnt;
        double var = r2[0] / cnt - mean * mean;
        if (var < 0.0) var = 0.0;
        stat[2 * s] = (float)mean;
        stat[2 * s + 1] = (float)(1.0 / sqrt(var + 1e-5));
    }
}

__global__ void k_seg_apply(const float* __restrict__ y, const float* __restrict__ stat,
                            const float* __restrict__ g, const float* __restrict__ bb,
                            float* __restrict__ hout, int S, int H, int total) {
    int idx = blockIdx.x * blockDim.x + threadIdx.x;
    if (idx >= total) return;
    int c = idx % H;
    int rr = idx / H;
    int v = rr % Vv;
    int s = (rr / Vv) % S;
    int nm = rr / (Vv * S);
    int b = nm * Vv + v;
    float val = (y[((size_t)b * S + s) * H + c] - stat[2 * s]) * stat[2 * s + 1] * g[s] + bb[s];
    hout[idx] = val;
}

__global__ void k_final(const float* __restrict__ y2, const float* __restrict__ stat,
                        const float* __restrict__ g, const float* __restrict__ bb,
                        const float* __restrict__ fcW, const float* __restrict__ fcb,
                        float* __restrict__ out) {
    __shared__ float pooled[C2];
    int n = blockIdx.x;
    for (int o = threadIdx.x; o < C2; o += blockDim.x) {
        float acc = 0.f;
        for (int m = 0; m < 2; m++)
            for (int v = 0; v < Vv; v++) {
                int b = (n * 2 + m) * Vv + v;
                for (int s = 0; s < S2n; s++) {
                    float val = (y2[((size_t)b * S2n + s) * C2 + o] - stat[2 * s]) * stat[2 * s + 1] * g[s] + bb[s];
                    acc += val;
                }
            }
        pooled[o] = acc / (2.f * Vv * S2n);
    }
    __syncthreads();
    for (int cls = threadIdx.x; cls < NCLS; cls += blockDim.x) {
        float acc = fcb[cls];
        for (int o = 0; o < C2; o++) acc += pooled[o] * fcW[cls * C2 + o];
        out[n * NCLS + cls] = acc;
    }
}

// ======================= host =======================

static void make_segs(int T, int S, Seg& seg, int& L) {
    double delta = (double)(T - 1) / (double)S;
    int tv[65];
    for (int i = 0; i <= S; i++) {
        double v = 1.0 + delta * (double)i;
        tv[i] = (int)nearbyint(v);
    }
    tv[S] = T;
    L = 0;
    for (int s = 0; s < S; s++) {
        seg.starts[s] = tv[s] - 1;
        seg.ends[s] = tv[s + 1] - 1;
        int len = seg.ends[s] - seg.starts[s] + 1;
        if (len > L) L = len;
    }
    if (L > 4) L = 4;
}

extern "C" void kernel_launch(void* const* d_in, const int* in_sizes, int n_in,
                              void* d_out, int out_size) {
    (void)in_sizes; (void)n_in; (void)out_size;
    const float* x        = (const float*)d_in[0];
    const float* dbn_g    = (const float*)d_in[2];
    const float* dbn_b    = (const float*)d_in[3];
    const float* Ap1      = (const float*)d_in[4];
    const float* Ar1      = (const float*)d_in[5];
    const float* W1       = (const float*)d_in[6];
    const float* b1       = (const float*)d_in[7];
    const float* bn1_g    = (const float*)d_in[8];
    const float* bn1_b    = (const float*)d_in[9];
    const float* Wih1     = (const float*)d_in[10];
    const float* Whh1     = (const float*)d_in[11];
    const float* bih1     = (const float*)d_in[12];
    const float* bhh1     = (const float*)d_in[13];
    const float* bs1_g    = (const float*)d_in[14];
    const float* bs1_b    = (const float*)d_in[15];
    const float* Ap2      = (const float*)d_in[16];
    const float* Ar2      = (const float*)d_in[17];
    const float* W2       = (const float*)d_in[18];
    const float* b2       = (const float*)d_in[19];
    const float* bn2_g    = (const float*)d_in[20];
    const float* bn2_b    = (const float*)d_in[21];
    const float* Wih2     = (const float*)d_in[22];
    const float* Whh2     = (const float*)d_in[23];
    const float* bih2     = (const float*)d_in[24];
    const float* bhh2     = (const float*)d_in[25];
    const float* bs2_g    = (const float*)d_in[26];
    const float* bs2_b    = (const float*)d_in[27];
    const float* fcW      = (const float*)d_in[28];
    const float* fcb      = (const float*)d_in[29];
    float* out = (float*)d_out;

    float *p_h0, *p_stat0, *p_S1, *p_O1, *p_stat1, *p_seq1, *p_xp1, *p_WT1, *p_y1,
          *p_ss1, *p_h1b, *p_O2, *p_stat2, *p_seq2, *p_xp2, *p_WT2, *p_y2, *p_ss2;
    __half *p_f1h, *p_f2h, *p_W1h_hi, *p_W1h_lo, *p_W2ih_hi, *p_W2ih_lo;
    __nv_bfloat16 *p_W2hi, *p_W2lo, *p_S2hi, *p_S2lo;
    cudaGetSymbolAddress((void**)&p_h0, g_h0);
    cudaGetSymbolAddress((void**)&p_stat0, g_stat0);
    cudaGetSymbolAddress((void**)&p_S1, g_S1);
    cudaGetSymbolAddress((void**)&p_O1, g_O1);
    cudaGetSymbolAddress((void**)&p_stat1, g_stat1);
    cudaGetSymbolAddress((void**)&p_seq1, g_seq1);
    cudaGetSymbolAddress((void**)&p_xp1, g_xp1);
    cudaGetSymbolAddress((void**)&p_WT1, g_WT1);
    cudaGetSymbolAddress((void**)&p_y1, g_y1);
    cudaGetSymbolAddress((void**)&p_ss1, g_sstat1);
    cudaGetSymbolAddress((void**)&p_h1b, g_h1b);
    cudaGetSymbolAddress((void**)&p_O2, g_O2);
    cudaGetSymbolAddress((void**)&p_stat2, g_stat2);
    cudaGetSymbolAddress((void**)&p_seq2, g_seq2);
    cudaGetSymbolAddress((void**)&p_xp2, g_xp2);
    cudaGetSymbolAddress((void**)&p_WT2, g_WT2);
    cudaGetSymbolAddress((void**)&p_y2, g_y2);
    cudaGetSymbolAddress((void**)&p_ss2, g_sstat2);
    cudaGetSymbolAddress((void**)&p_f1h, g_f1h);
    cudaGetSymbolAddress((void**)&p_f2h, g_f2h);
    cudaGetSymbolAddress((void**)&p_W1h_hi, g_W1h_hi);
    cudaGetSymbolAddress((void**)&p_W1h_lo, g_W1h_lo);
    cudaGetSymbolAddress((void**)&p_W2ih_hi, g_W2ih_hi);
    cudaGetSymbolAddress((void**)&p_W2ih_lo, g_W2ih_lo);
    cudaGetSymbolAddress((void**)&p_W2hi, g_W2hi);
    cudaGetSymbolAddress((void**)&p_W2lo, g_W2lo);
    cudaGetSymbolAddress((void**)&p_S2hi, g_S2hi);
    cudaGetSymbolAddress((void**)&p_S2lo, g_S2lo);

    Seg seg1, seg2; int L1, L2;
    make_segs(Tt, S1n, seg1, L1);
    make_segs(S1n, S2n, seg2, L2);

    // weight prep
    k_transpose<<<(4 * C1 * C1 + 255) / 256, 256>>>(Whh1, p_WT1, 4 * C1, C1);
    k_transpose<<<(4 * C2 * C2 + 255) / 256, 256>>>(Whh2, p_WT2, 4 * C2, C2);
    k_cvt_f16split<<<(384 * KP1 + 255) / 256, 256>>>(Wih1, p_W1h_hi, p_W1h_lo, 384, IN1, KP1);
    k_cvt_f16split<<<(768 * IN2 + 255) / 256, 256>>>(Wih2, p_W2ih_hi, p_W2ih_lo, 768, IN2, IN2);
    k_cvt_bfsplit<<<(192 * KG2 + 255) / 256, 256>>>(W2, p_W2hi, p_W2lo, 192 * KG2);

    // ---- data BN ----
    k_bn0_stats<<<150, 256>>>(x, p_stat0);
    k_bn0_apply<<<(NM * Tt * Vv * Cin + 255) / 256, 256>>>(x, p_stat0, dbn_g, dbn_b, p_h0);

    // ---- GCN 1 (fp32) ----
    k_gcn_support<<<NM * Tt, 256, Vv * Cin * sizeof(float)>>>(p_h0, Ap1, Ar1, p_S1, Tt, Cin);
    {
        dim3 grid((C1 + TBN - 1) / TBN, (NM * Tt * Vv + TBM - 1) / TBM);
        k_gemm_abt<<<grid, 256>>>(p_S1, W1, b1, p_O1, NM * Tt * Vv, C1, Kk * Cin);
    }
    k_colstats<<<C1, 256>>>(p_O1, p_stat1, NM * Tt * Vv, C1);
    k_bn_relu_seq<<<(NM * Tt * Vv * C1 + 255) / 256, 256>>>(p_O1, p_stat1, bn1_g, bn1_b, p_seq1, Tt, C1, NM * Tt * Vv * C1);

    // ---- logsig + LSTM 1 ----
    k_feats_f16<<<100 * S1n, 256>>>(p_seq1, p_f1h, Tt, C1, S1n, IN1, KP1, seg1);
    {
        int smem = GF_STAGES * (128 * GF_LDA + 2 * 128 * GF_LDA) * (int)sizeof(__half);
        cudaFuncSetAttribute(k_gemm_f16, cudaFuncAttributeMaxDynamicSharedMemorySize, smem);
        dim3 grid(384 / 128, (5000 + 127) / 128);
        k_gemm_f16<<<grid, 256, smem>>>(p_f1h, p_W1h_hi, p_W1h_lo, bih1, bhh1, p_xp1, 5000, 384, KP1);
    }
    int smem1 = (6 * C1 + C1 * 4 * C1) * (int)sizeof(float);
    cudaFuncSetAttribute(k_lstm, cudaFuncAttributeMaxDynamicSharedMemorySize, smem1);
    k_lstm<<<100, 4 * C1, smem1>>>(p_xp1, p_WT1, p_y1, S1n, C1, 1);
    k_seg_stats<<<S1n, 256>>>(p_y1, p_ss1, S1n, C1);
    k_seg_apply<<<(NM * S1n * Vv * C1 + 255) / 256, 256>>>(p_y1, p_ss1, bs1_g, bs1_b, p_h1b, S1n, C1, NM * S1n * Vv * C1);

    // ---- GCN 2 (bf16 3-pass tensor path) ----
    k_gcn_support_bf<<<NM * S1n, 256, Vv * C1 * sizeof(float)>>>(p_h1b, Ap2, Ar2, p_S2hi, p_S2lo, S1n, C1);
    {
        dim3 grid(192 / 64, (5000 + 63) / 64);
        k_mma_gemm_bf<<<grid, 128>>>(p_S2hi, p_S2lo, p_W2hi, p_W2lo, b2, p_O2, 5000, 192, KG2);
    }
    k_colstats<<<C2, 256>>>(p_O2, p_stat2, NM * S1n * Vv, C2);
    k_bn_relu_seq<<<(NM * S1n * Vv * C2 + 255) / 256, 256>>>(p_O2, p_stat2, bn2_g, bn2_b, p_seq2, S1n, C2, NM * S1n * Vv * C2);

    // ---- logsig + LSTM 2 ----
    k_feats_f16<<<100 * S2n, 256>>>(p_seq2, p_f2h, S1n, C2, S2n, IN2, IN2, seg2);
    {
        int smem = GF_STAGES * (128 * GF_LDA + 2 * 128 * GF_LDA) * (int)sizeof(__half);
        dim3 grid(768 / 128, (3000 + 127) / 128);
        k_gemm_f16<<<grid, 256, smem>>>(p_f2h, p_W2ih_hi, p_W2ih_lo, bih2, bhh2, p_xp2, 3000, 768, IN2);
    }
    int smem2 = 6 * C2 * (int)sizeof(float);
    k_lstm<<<100, 4 * C2, smem2>>>(p_xp2, p_WT2, p_y2, S2n, C2, 0);
    k_seg_stats<<<S2n, 256>>>(p_y2, p_ss2, S2n, C2);

    // ---- pooling + fc ----
    k_final<<<Nn, 256>>>(p_y2, p_ss2, bs2_g, bs2_b, fcW, fcb, out);
}

// round 4
// speedup vs baseline: 4.8118x; 1.2764x over previous
#include <cuda_runtime.h>
#include <cuda_bf16.h>
#include <cuda_fp16.h>
#include <cmath>
#include <cstdint>

// ======================= model constants =======================
#define Nn    2
#define Mm_   2
#define NM    4
#define Cin   3
#define Tt    100
#define Vv    25
#define Kk    13
#define C1    96
#define C2    192
#define S1n   50
#define S2n   30
#define IN1   4752     // 2*96 + 4560
#define IN2   18720    // 2*192 + 18336
#define KP1   4768     // IN1 padded to /32
#define KG2   1248     // 13*96
#define NCLS  60

struct Seg { int starts[64]; int ends[64]; };

// ======================= device scratch ========================
__device__ float g_h0[NM*Tt*Vv*Cin];
__device__ float g_stat0[150*2];
__device__ float g_S1[NM*Tt*Vv*Kk*Cin];
__device__ float g_O1[NM*Tt*Vv*C1];
__device__ float g_stat1[C1*2];
__device__ float g_seq1[100*Tt*C1];
__device__ float g_xp1[5000*4*C1];
__device__ float g_WT1[C1*4*C1];
__device__ float g_y1[100*S1n*C1];
__device__ float g_sstat1[S1n*2];
__device__ float g_h1b[NM*S1n*Vv*C1];
__device__ float g_O2[NM*S1n*Vv*C2];
__device__ float g_stat2[C2*2];
__device__ float g_seq2[100*S1n*C2];
__device__ float g_xp2[3000*4*C2];
__device__ float g_WT2[C2*4*C2];
__device__ float g_y2[100*S2n*C2];
__device__ float g_sstat2[S2n*2];

// f16 operands for the two big xp GEMMs (A single, B hi/lo)
__device__ __half g_f1h[5000*KP1];
__device__ __half g_f2h[3000*IN2];
__device__ __half g_W1h_hi[384*KP1], g_W1h_lo[384*KP1];
__device__ __half g_W2ih_hi[768*IN2], g_W2ih_lo[768*IN2];

// bf16 hi/lo operands for gcn2 GEMM (3-pass, extra-safe)
__device__ __nv_bfloat16 g_W2hi[192*KG2],  g_W2lo[192*KG2];
__device__ __nv_bfloat16 g_S2hi[5000*KG2], g_S2lo[5000*KG2];

// ======================= helpers ===============================

__device__ __forceinline__ void st_split_bf(__nv_bfloat16* hi, __nv_bfloat16* lo, size_t i, float v) {
    __nv_bfloat16 h = __float2bfloat16(v);
    hi[i] = h;
    lo[i] = __float2bfloat16(v - __bfloat162float(h));
}

__device__ __forceinline__ void cp_async16(void* smem, const void* gmem) {
    uint32_t s = (uint32_t)__cvta_generic_to_shared(smem);
    asm volatile("cp.async.cg.shared.global [%0], [%1], 16;\n" :: "r"(s), "l"(gmem));
}
#define CP_COMMIT() asm volatile("cp.async.commit_group;\n" ::: "memory")
#define CP_WAIT1()  asm volatile("cp.async.wait_group 1;\n" ::: "memory")

__device__ __forceinline__ void mma16816_bf(float* d, const uint32_t* a, const uint32_t* b) {
    asm volatile(
        "mma.sync.aligned.m16n8k16.row.col.f32.bf16.bf16.f32 "
        "{%0,%1,%2,%3}, {%4,%5,%6,%7}, {%8,%9}, {%0,%1,%2,%3};"
        : "+f"(d[0]), "+f"(d[1]), "+f"(d[2]), "+f"(d[3])
        : "r"(a[0]), "r"(a[1]), "r"(a[2]), "r"(a[3]), "r"(b[0]), "r"(b[1]));
}

__device__ __forceinline__ void mma16816_f16(float* d, const uint32_t* a, uint32_t b0, uint32_t b1) {
    asm volatile(
        "mma.sync.aligned.m16n8k16.row.col.f32.f16.f16.f32 "
        "{%0,%1,%2,%3}, {%4,%5,%6,%7}, {%8,%9}, {%0,%1,%2,%3};"
        : "+f"(d[0]), "+f"(d[1]), "+f"(d[2]), "+f"(d[3])
        : "r"(a[0]), "r"(a[1]), "r"(a[2]), "r"(a[3]), "r"(b0), "r"(b1));
}

#define LDSM4(r0, r1, r2, r3, addr) \
    asm volatile("ldmatrix.sync.aligned.m8n8.x4.shared.b16 {%0,%1,%2,%3}, [%4];" \
        : "=r"(r0), "=r"(r1), "=r"(r2), "=r"(r3) : "r"(addr))

// ======================= small kernels =========================

__global__ void k_transpose(const float* __restrict__ W, float* __restrict__ WT, int G, int H) {
    int idx = blockIdx.x * blockDim.x + threadIdx.x;
    if (idx < G * H) {
        int j = idx / H, k = idx % H;
        WT[k * G + j] = W[j * H + k];
    }
}

// fp32 (N,K) -> f16 hi/lo (N,Kpad), zero tail (generic, Kpad may != K)
__global__ void k_cvt_f16split(const float* __restrict__ W, __half* __restrict__ hi,
                               __half* __restrict__ lo, int Nrows, int K, int Kpad) {
    int idx = blockIdx.x * blockDim.x + threadIdx.x;
    if (idx >= Nrows * Kpad) return;
    int n = idx / Kpad, k = idx % Kpad;
    float v = (k < K) ? W[(size_t)n * K + k] : 0.f;
    __half h = __float2half_rn(v);
    hi[idx] = h;
    lo[idx] = __float2half_rn(v - __half2float(h));
}

// vectorized f16 split, Kpad == K, total % 4 == 0
__global__ void k_cvt_f16split_v4(const float4* __restrict__ W, uint2* __restrict__ hi,
                                  uint2* __restrict__ lo, int total4) {
    int idx = blockIdx.x * blockDim.x + threadIdx.x;
    if (idx >= total4) return;
    float4 v = W[idx];
    __half h0 = __float2half_rn(v.x), h1 = __float2half_rn(v.y);
    __half h2 = __float2half_rn(v.z), h3 = __float2half_rn(v.w);
    __half l0 = __float2half_rn(v.x - __half2float(h0));
    __half l1 = __float2half_rn(v.y - __half2float(h1));
    __half l2 = __float2half_rn(v.z - __half2float(h2));
    __half l3 = __float2half_rn(v.w - __half2float(h3));
    uint2 ho, loo;
    ho.x  = (uint32_t)__half_as_ushort(h0) | ((uint32_t)__half_as_ushort(h1) << 16);
    ho.y  = (uint32_t)__half_as_ushort(h2) | ((uint32_t)__half_as_ushort(h3) << 16);
    loo.x = (uint32_t)__half_as_ushort(l0) | ((uint32_t)__half_as_ushort(l1) << 16);
    loo.y = (uint32_t)__half_as_ushort(l2) | ((uint32_t)__half_as_ushort(l3) << 16);
    hi[idx] = ho;
    lo[idx] = loo;
}

// fp32 -> bf16 hi/lo
__global__ void k_cvt_bfsplit(const float* __restrict__ W, __nv_bfloat16* __restrict__ hi,
                              __nv_bfloat16* __restrict__ lo, int total) {
    int idx = blockIdx.x * blockDim.x + threadIdx.x;
    if (idx >= total) return;
    st_split_bf(hi, lo, idx, W[idx]);
}

__global__ void k_bn0_stats(const float* __restrict__ x, float* __restrict__ stat) {
    int ch = blockIdx.x;
    int m = ch / (Vv * Cin);
    int v = (ch / Cin) % Vv;
    int c = ch % Cin;
    double s = 0.0, ss = 0.0;
    for (int i = threadIdx.x; i < Nn * Tt; i += blockDim.x) {
        int n = i / Tt, t = i % Tt;
        float val = x[(((n * Cin + c) * Tt + t) * Vv + v) * Mm_ + m];
        s += val; ss += (double)val * val;
    }
    __shared__ double r1[256], r2[256];
    r1[threadIdx.x] = s; r2[threadIdx.x] = ss;
    __syncthreads();
    for (int off = 128; off > 0; off >>= 1) {
        if (threadIdx.x < off) { r1[threadIdx.x] += r1[threadIdx.x + off]; r2[threadIdx.x] += r2[threadIdx.x + off]; }
        __syncthreads();
    }
    if (threadIdx.x == 0) {
        double cnt = (double)(Nn * Tt);
        double mean = r1[0] / cnt;
        double var = r2[0] / cnt - mean * mean;
        if (var < 0.0) var = 0.0;
        stat[2 * ch] = (float)mean;
        stat[2 * ch + 1] = (float)(1.0 / sqrt(var + 1e-5));
    }
}

__global__ void k_bn0_apply(const float* __restrict__ x, const float* __restrict__ stat,
                            const float* __restrict__ g, const float* __restrict__ b,
                            float* __restrict__ h0) {
    int idx = blockIdx.x * blockDim.x + threadIdx.x;
    if (idx >= NM * Tt * Vv * Cin) return;
    int c = idx % Cin;
    int v = (idx / Cin) % Vv;
    int t = (idx / (Cin * Vv)) % Tt;
    int nm = idx / (Cin * Vv * Tt);
    int n = nm >> 1, m = nm & 1;
    int ch = m * (Vv * Cin) + v * Cin + c;
    float val = x[(((n * Cin + c) * Tt + t) * Vv + v) * Mm_ + m];
    h0[idx] = (val - stat[2 * ch]) * stat[2 * ch + 1] * g[ch] + b[ch];
}

// fp32 support (layer 1)
__global__ void k_gcn_support(const float* __restrict__ hin, const float* __restrict__ Ap,
                              const float* __restrict__ Ares, float* __restrict__ Sout,
                              int T, int Cc) {
    __shared__ float Asm[325 * 25];
    extern __shared__ float hsm[];
    int blk = blockIdx.x;
    for (int i = threadIdx.x; i < 325 * 25; i += blockDim.x) Asm[i] = Ap[i] + Ares[i];
    const float* hrow = hin + (size_t)blk * Vv * Cc;
    for (int i = threadIdx.x; i < Vv * Cc; i += blockDim.x) hsm[i] = hrow[i];
    __syncthreads();
    int tot = Vv * Kk * Cc;
    float* outrow = Sout + (size_t)blk * tot;
    for (int f = threadIdx.x; f < tot; f += blockDim.x) {
        int c = f % Cc;
        int k = (f / Cc) % Kk;
        int v = f / (Kk * Cc);
        const float* arow = Asm + (k * Vv + v) * Vv;
        float acc = 0.f;
        #pragma unroll
        for (int u = 0; u < Vv; u++) acc += arow[u] * hsm[u * Cc + c];
        outrow[f] = acc;
    }
}

// bf16 hi/lo support (layer 2)
__global__ void k_gcn_support_bf(const float* __restrict__ hin, const float* __restrict__ Ap,
                                 const float* __restrict__ Ares, __nv_bfloat16* __restrict__ Shi,
                                 __nv_bfloat16* __restrict__ Slo, int T, int Cc) {
    __shared__ float Asm[325 * 25];
    extern __shared__ float hsm[];
    int blk = blockIdx.x;
    for (int i = threadIdx.x; i < 325 * 25; i += blockDim.x) Asm[i] = Ap[i] + Ares[i];
    const float* hrow = hin + (size_t)blk * Vv * Cc;
    for (int i = threadIdx.x; i < Vv * Cc; i += blockDim.x) hsm[i] = hrow[i];
    __syncthreads();
    int tot = Vv * Kk * Cc;
    size_t base = (size_t)blk * tot;
    for (int f = threadIdx.x; f < tot; f += blockDim.x) {
        int c = f % Cc;
        int k = (f / Cc) % Kk;
        int v = f / (Kk * Cc);
        const float* arow = Asm + (k * Vv + v) * Vv;
        float acc = 0.f;
        #pragma unroll
        for (int u = 0; u < Vv; u++) acc += arow[u] * hsm[u * Cc + c];
        st_split_bf(Shi, Slo, base + f, acc);
    }
}

// fp32 GEMM (gcn1 only)
#define TBM 64
#define TBN 64
#define TBK 16
__global__ void k_gemm_abt(const float* __restrict__ A, const float* __restrict__ B,
                           const float* __restrict__ bias1,
                           float* __restrict__ C, int M, int N, int K) {
    __shared__ float As[TBK][TBM];
    __shared__ float Bs[TBK][TBN];
    int m0 = blockIdx.y * TBM;
    int n0 = blockIdx.x * TBN;
    int tid = threadIdx.x;
    int tx = tid & 15, ty = tid >> 4;
    float acc[4][4] = {};
    for (int kt = 0; kt < K; kt += TBK) {
        #pragma unroll
        for (int e = 0; e < 4; e++) {
            int idx = tid + e * 256;
            int r = idx >> 4, c = idx & 15;
            int gk = kt + c;
            int gm = m0 + r;
            As[c][r] = (gm < M && gk < K) ? A[(size_t)gm * K + gk] : 0.f;
            int gn = n0 + r;
            Bs[c][r] = (gn < N && gk < K) ? B[(size_t)gn * K + gk] : 0.f;
        }
        __syncthreads();
        #pragma unroll
        for (int kk = 0; kk < TBK; kk++) {
            float4 a4 = *reinterpret_cast<const float4*>(&As[kk][ty * 4]);
            float4 b4 = *reinterpret_cast<const float4*>(&Bs[kk][tx * 4]);
            float av[4] = {a4.x, a4.y, a4.z, a4.w};
            float bv[4] = {b4.x, b4.y, b4.z, b4.w};
            #pragma unroll
            for (int r = 0; r < 4; r++)
                #pragma unroll
                for (int c = 0; c < 4; c++) acc[r][c] += av[r] * bv[c];
        }
        __syncthreads();
    }
    #pragma unroll
    for (int r = 0; r < 4; r++) {
        int gm = m0 + ty * 4 + r;
        if (gm >= M) continue;
        #pragma unroll
        for (int c = 0; c < 4; c++) {
            int gn = n0 + tx * 4 + c;
            if (gn >= N) continue;
            C[(size_t)gm * N + gn] = acc[r][c] + (bias1 ? bias1[gn] : 0.f);
        }
    }
}

// ====== bf16 3-pass tensor GEMM (gcn2): 64x64 tile, 128 thr ======
__global__ void __launch_bounds__(128) k_mma_gemm_bf(
    const __nv_bfloat16* __restrict__ Ahi, const __nv_bfloat16* __restrict__ Alo,
    const __nv_bfloat16* __restrict__ Bhi, const __nv_bfloat16* __restrict__ Blo,
    const float* __restrict__ bias1,
    float* __restrict__ C, int M, int N, int K)
{
    __shared__ __nv_bfloat16 sA[2][2][64][40];
    __shared__ __nv_bfloat16 sB[2][2][64][40];
    const int m0 = blockIdx.y * 64, n0 = blockIdx.x * 64;
    const int tid = threadIdx.x;
    const int lane = tid & 31, warp = tid >> 5;
    const int wm = (warp & 1) * 32, wn = (warp >> 1) * 32;
    const int r = lane >> 2, s2 = (lane & 3) * 2;
    float acc[2][4][4];
    #pragma unroll
    for (int a = 0; a < 2; a++)
        #pragma unroll
        for (int b = 0; b < 4; b++)
            #pragma unroll
            for (int c = 0; c < 4; c++) acc[a][b][c] = 0.f;

    const int srow = tid >> 2;
    const int schk = (tid & 3) * 8;
    const int nk = K >> 5;

    #pragma unroll
    for (int h = 0; h < 2; h++) {
        int row = srow + h * 32;
        int ga = m0 + row; if (ga >= M) ga = M - 1;
        int gb = n0 + row; if (gb >= N) gb = N - 1;
        cp_async16(&sA[0][0][row][schk], Ahi + (size_t)ga * K + schk);
        cp_async16(&sA[0][1][row][schk], Alo + (size_t)ga * K + schk);
        cp_async16(&sB[0][0][row][schk], Bhi + (size_t)gb * K + schk);
        cp_async16(&sB[0][1][row][schk], Blo + (size_t)gb * K + schk);
    }
    CP_COMMIT();

    for (int kc = 0; kc < nk; kc++) {
        int st = kc & 1;
        if (kc + 1 < nk) {
            int kt = (kc + 1) << 5;
            int sn = st ^ 1;
            #pragma unroll
            for (int h = 0; h < 2; h++) {
                int row = srow + h * 32;
                int ga = m0 + row; if (ga >= M) ga = M - 1;
                int gb = n0 + row; if (gb >= N) gb = N - 1;
                cp_async16(&sA[sn][0][row][schk], Ahi + (size_t)ga * K + kt + schk);
                cp_async16(&sA[sn][1][row][schk], Alo + (size_t)ga * K + kt + schk);
                cp_async16(&sB[sn][0][row][schk], Bhi + (size_t)gb * K + kt + schk);
                cp_async16(&sB[sn][1][row][schk], Blo + (size_t)gb * K + kt + schk);
            }
        }
        CP_COMMIT();
        CP_WAIT1();
        __syncthreads();

        #pragma unroll
        for (int ks = 0; ks < 2; ks++) {
            const int kb = ks * 16 + s2;
            uint32_t ah[2][4], al[2][4];
            #pragma unroll
            for (int mt = 0; mt < 2; mt++) {
                int row = wm + mt * 16 + r;
                const __nv_bfloat16* p0 = &sA[st][0][row][kb];
                const __nv_bfloat16* p1 = &sA[st][0][row + 8][kb];
                ah[mt][0] = *(const uint32_t*)p0;
                ah[mt][1] = *(const uint32_t*)p1;
                ah[mt][2] = *(const uint32_t*)(p0 + 8);
                ah[mt][3] = *(const uint32_t*)(p1 + 8);
                const __nv_bfloat16* q0 = &sA[st][1][row][kb];
                const __nv_bfloat16* q1 = &sA[st][1][row + 8][kb];
                al[mt][0] = *(const uint32_t*)q0;
                al[mt][1] = *(const uint32_t*)q1;
                al[mt][2] = *(const uint32_t*)(q0 + 8);
                al[mt][3] = *(const uint32_t*)(q1 + 8);
            }
            #pragma unroll
            for (int nt = 0; nt < 4; nt++) {
                int nrow = wn + nt * 8 + r;
                uint32_t bh[2], bl[2];
                const __nv_bfloat16* p = &sB[st][0][nrow][kb];
                bh[0] = *(const uint32_t*)p;
                bh[1] = *(const uint32_t*)(p + 8);
                const __nv_bfloat16* q = &sB[st][1][nrow][kb];
                bl[0] = *(const uint32_t*)q;
                bl[1] = *(const uint32_t*)(q + 8);
                #pragma unroll
                for (int mt = 0; mt < 2; mt++) {
                    mma16816_bf(acc[mt][nt], ah[mt], bh);
                    mma16816_bf(acc[mt][nt], ah[mt], bl);
                    mma16816_bf(acc[mt][nt], al[mt], bh);
                }
            }
        }
        __syncthreads();
    }

    #pragma unroll
    for (int mt = 0; mt < 2; mt++) {
        int gm = m0 + wm + mt * 16 + r;
        #pragma unroll
        for (int nt = 0; nt < 4; nt++) {
            int gn = n0 + wn + nt * 8 + s2;
            if (gn >= N) continue;
            float bv0 = bias1 ? bias1[gn] : 0.f;
            float bv1 = bias1 ? bias1[gn + 1] : 0.f;
            if (gm < M) {
                C[(size_t)gm * N + gn]     = acc[mt][nt][0] + bv0;
                C[(size_t)gm * N + gn + 1] = acc[mt][nt][1] + bv1;
            }
            if (gm + 8 < M) {
                C[(size_t)(gm + 8) * N + gn]     = acc[mt][nt][2] + bv0;
                C[(size_t)(gm + 8) * N + gn + 1] = acc[mt][nt][3] + bv1;
            }
        }
    }
}

// ====== f16 2-pass tensor GEMM (xp1/xp2): 128x128 tile, 256 thr, ldmatrix, 3-stage ======
#define GF_STAGES 3
#define GF_LDA 40
__global__ void __launch_bounds__(256) k_gemm_f16(
    const __half* __restrict__ A,
    const __half* __restrict__ Bhi, const __half* __restrict__ Blo,
    const float* __restrict__ bias1, const float* __restrict__ bias2,
    float* __restrict__ C, int M, int N, int K)
{
    extern __shared__ __half smem[];
    __half* sA = smem;                              // [GF_STAGES][128][GF_LDA]
    __half* sB = smem + GF_STAGES * 128 * GF_LDA;   // [GF_STAGES][2][128][GF_LDA]

    const int m0 = blockIdx.y * 128, n0 = blockIdx.x * 128;
    const int tid = threadIdx.x;
    const int lane = tid & 31, warp = tid >> 5;
    const int wm = (warp & 1) * 64;
    const int wn = (warp >> 1) * 32;
    const int nk = K >> 5;

    const uint32_t sA_u = (uint32_t)__cvta_generic_to_shared(sA);
    const uint32_t sB_u = (uint32_t)__cvta_generic_to_shared(sB);

    const int lrow = lane & 15;
    const int lkh  = (lane >> 4) << 3;
    const int brow = ((lane >> 4) << 3) + (lane & 7);
    const int bkh  = ((lane >> 3) & 1) << 3;

    float acc[4][4][4];
    #pragma unroll
    for (int a = 0; a < 4; a++)
        #pragma unroll
        for (int b = 0; b < 4; b++)
            #pragma unroll
            for (int c = 0; c < 4; c++) acc[a][b][c] = 0.f;

    auto load_stage = [&](int st, int kt) {
        #pragma unroll
        for (int e = 0; e < 2; e++) {
            int i = tid + e * 256;
            int row = i >> 2, chk = (i & 3) << 3;
            int ga = m0 + row; if (ga >= M) ga = M - 1;
            cp_async16(&sA[(st * 128 + row) * GF_LDA + chk], A + (size_t)ga * K + kt + chk);
        }
        #pragma unroll
        for (int e = 0; e < 2; e++) {
            int i = tid + e * 256;
            int row = i >> 2, chk = (i & 3) << 3;
            int gb = n0 + row; if (gb >= N) gb = N - 1;
            cp_async16(&sB[((st * 2 + 0) * 128 + row) * GF_LDA + chk], Bhi + (size_t)gb * K + kt + chk);
            cp_async16(&sB[((st * 2 + 1) * 128 + row) * GF_LDA + chk], Blo + (size_t)gb * K + kt + chk);
        }
    };

    load_stage(0, 0);
    CP_COMMIT();
    load_stage(1, 32);
    CP_COMMIT();

    for (int kc = 0; kc < nk; kc++) {
        int st = kc % GF_STAGES;
        CP_WAIT1();
        __syncthreads();
        if (kc + 2 < nk) {
            load_stage((kc + 2) % GF_STAGES, (kc + 2) << 5);
            CP_COMMIT();
        }

        #pragma unroll
        for (int ks = 0; ks < 2; ks++) {
            const int kb = ks * 16;
            uint32_t a[4][4];
            #pragma unroll
            for (int mt = 0; mt < 4; mt++) {
                uint32_t addr = sA_u + (((st * 128) + wm + mt * 16 + lrow) * GF_LDA + kb + lkh) * 2;
                LDSM4(a[mt][0], a[mt][1], a[mt][2], a[mt][3], addr);
            }
            #pragma unroll
            for (int g = 0; g < 2; g++) {
                uint32_t bh0, bh1, bh2, bh3, bl0, bl1, bl2, bl3;
                uint32_t addr_h = sB_u + ((((st * 2 + 0) * 128) + wn + g * 16 + brow) * GF_LDA + kb + bkh) * 2;
                uint32_t addr_l = sB_u + ((((st * 2 + 1) * 128) + wn + g * 16 + brow) * GF_LDA + kb + bkh) * 2;
                LDSM4(bh0, bh1, bh2, bh3, addr_h);
                LDSM4(bl0, bl1, bl2, bl3, addr_l);
                #pragma unroll
                for (int mt = 0; mt < 4; mt++) {
                    mma16816_f16(acc[mt][2 * g],     a[mt], bh0, bh1);
                    mma16816_f16(acc[mt][2 * g + 1], a[mt], bh2, bh3);
                    mma16816_f16(acc[mt][2 * g],     a[mt], bl0, bl1);
                    mma16816_f16(acc[mt][2 * g + 1], a[mt], bl2, bl3);
                }
            }
        }
        __syncthreads();
    }

    const int r = lane >> 2, cp = (lane & 3) * 2;
    #pragma unroll
    for (int mt = 0; mt < 4; mt++) {
        int gm = m0 + wm + mt * 16 + r;
        #pragma unroll
        for (int nt = 0; nt < 4; nt++) {
            int gn = n0 + wn + nt * 8 + cp;
            float bv0 = 0.f, bv1 = 0.f;
            if (bias1) { bv0 += bias1[gn]; bv1 += bias1[gn + 1]; }
            if (bias2) { bv0 += bias2[gn]; bv1 += bias2[gn + 1]; }
            if (gm < M) {
                C[(size_t)gm * N + gn]     = acc[mt][nt][0] + bv0;
                C[(size_t)gm * N + gn + 1] = acc[mt][nt][1] + bv1;
            }
            if (gm + 8 < M) {
                C[(size_t)(gm + 8) * N + gn]     = acc[mt][nt][2] + bv0;
                C[(size_t)(gm + 8) * N + gn + 1] = acc[mt][nt][3] + bv1;
            }
        }
    }
}

// ======================= elementwise chain =====================

__global__ void k_colstats(const float* __restrict__ X, float* __restrict__ stat, int Mrows, int Ncols) {
    int col = blockIdx.x;
    double s = 0.0, ss = 0.0;
    for (int rr = threadIdx.x; rr < Mrows; rr += blockDim.x) {
        float v = X[(size_t)rr * Ncols + col];
        s += v; ss += (double)v * v;
    }
    __shared__ double r1[256], r2[256];
    r1[threadIdx.x] = s; r2[threadIdx.x] = ss;
    __syncthreads();
    for (int off = 128; off > 0; off >>= 1) {
        if (threadIdx.x < off) { r1[threadIdx.x] += r1[threadIdx.x + off]; r2[threadIdx.x] += r2[threadIdx.x + off]; }
        __syncthreads();
    }
    if (threadIdx.x == 0) {
        double cnt = (double)Mrows;
        double mean = r1[0] / cnt;
        double var = r2[0] / cnt - mean * mean;
        if (var < 0.0) var = 0.0;
        stat[2 * col] = (float)mean;
        stat[2 * col + 1] = (float)(1.0 / sqrt(var + 1e-5));
    }
}

__global__ void k_bn_relu_seq(const float* __restrict__ O, const float* __restrict__ stat,
                              const float* __restrict__ g, const float* __restrict__ bb,
                              float* __restrict__ seq, int T, int Cc, int total) {
    int idx = blockIdx.x * blockDim.x + threadIdx.x;
    if (idx >= total) return;
    int c = idx % Cc;
    int j = idx / Cc;
    int v = j % Vv;
    int t = (j / Vv) % T;
    int nm = j / (Vv * T);
    float val = (O[idx] - stat[2 * c]) * stat[2 * c + 1] * g[c] + bb[c];
    val = fmaxf(val, 0.f);
    int b = nm * Vv + v;
    seq[((size_t)b * T + t) * Cc + c] = val;
}

// closed-form log-sig feats -> f16: [p0, p2-p0, 0.5*(u_i w_j - u_j w_i)]
// warp-per-row levy scheduling: lanes sweep j contiguously -> coalesced stores.
__global__ void k_feats_f16_v2(const float* __restrict__ seq, __half* __restrict__ f,
                               int T, int d, int S, int in_dim, int Kpad, Seg seg) {
    extern __shared__ float sm2[];    // su[d], w[d]
    float* s_su = sm2;
    float* s_w  = sm2 + d;
    int bs = blockIdx.x;
    int b = bs / S, s = bs % S;
    int st = seg.starts[s], en = seg.ends[s];
    int i1 = min(st + 1, en), i2 = min(st + 2, en);
    const float* x0 = seq + ((size_t)b * T + st) * d;
    const float* x1 = seq + ((size_t)b * T + i1) * d;
    const float* x2 = seq + ((size_t)b * T + i2) * d;
    __half* out = f + (size_t)bs * Kpad;
    int tid = threadIdx.x;
    for (int i = tid; i < d; i += blockDim.x) {
        float p0 = x0[i], p1 = x1[i], p2 = x2[i];
        s_su[i] = 0.5f * (p1 - p0);
        s_w[i]  = p2 - p1;
        out[i] = __float2half_rn(p0);
        out[d + i] = __float2half_rn(p2 - p0);
    }
    for (int i = in_dim + tid; i < Kpad; i += blockDim.x) out[i] = __ushort_as_half(0);
    __syncthreads();
    __half* lev = out + 2 * d;
    int npairs = in_dim - 2 * d;
    if (en - st < 2) {
        // levy all zero: vectorized fill (lev is 16B-aligned: d%8==0, npairs%8==0)
        uint4 z4; z4.x = z4.y = z4.z = z4.w = 0u;
        uint4* o4 = (uint4*)lev;
        int n8 = npairs >> 3;
        for (int i = tid; i < n8; i += blockDim.x) o4[i] = z4;
        return;
    }
    int lane = tid & 31, wp = tid >> 5, nw = blockDim.x >> 5;
    for (int i = wp; i < d - 1; i += nw) {
        float sui = s_su[i], wi = s_w[i];
        __half* row = lev + (size_t)i * (2 * d - i - 1) / 2 - (i + 1);
        for (int j = i + 1 + lane; j < d; j += 32) {
            float v = fmaf(sui, s_w[j], -(wi * s_su[j]));
            row[j] = __float2half_rn(v);
        }
    }
}

__device__ __forceinline__ float sigf(float x) { return 1.f / (1.f + expf(-x)); }

__global__ void k_lstm(const float* __restrict__ xp, const float* __restrict__ WT,
                       float* __restrict__ y, int S, int H, int stageW) {
    extern __shared__ float sm[];
    float* sh = sm;
    float* sc = sm + H;
    float* sg = sm + 2 * H;
    float* sW = sm + 6 * H;
    int b = blockIdx.x;
    int j = threadIdx.x;
    int G = 4 * H;
    if (stageW) {
        for (int idx = j; idx < H * G; idx += blockDim.x) sW[idx] = WT[idx];
    }
    if (j < H) { sh[j] = 0.f; sc[j] = 0.f; }
    __syncthreads();
    const float* W = stageW ? sW : WT;
    for (int s = 0; s < S; s++) {
        float g = xp[((size_t)b * S + s) * G + j];
        for (int k = 0; k < H; k++) g += sh[k] * W[k * G + j];
        sg[j] = g;
        __syncthreads();
        if (j < H) {
            float iv = sigf(sg[j]);
            float fv = sigf(sg[H + j]);
            float gv = tanhf(sg[2 * H + j]);
            float ov = sigf(sg[3 * H + j]);
            float cn = fv * sc[j] + iv * gv;
            sc[j] = cn;
            float hn = ov * tanhf(cn);
            sh[j] = hn;
            y[((size_t)b * S + s) * H + j] = hn;
        }
        __syncthreads();
    }
}

__global__ void k_seg_stats(const float* __restrict__ y, float* __restrict__ stat, int S, int H) {
    int s = blockIdx.x;
    double sum = 0.0, ssq = 0.0;
    for (int i = threadIdx.x; i < 100 * H; i += blockDim.x) {
        int b = i / H, h = i % H;
        float v = y[((size_t)b * S + s) * H + h];
        sum += v; ssq += (double)v * v;
    }
    __shared__ double r1[256], r2[256];
    r1[threadIdx.x] = sum; r2[threadIdx.x] = ssq;
    __syncthreads();
    for (int off = 128; off > 0; off >>= 1) {
        if (threadIdx.x < off) { r1[threadIdx.x] += r1[threadIdx.x + off]; r2[threadIdx.x] += r2[threadIdx.x + off]; }
        __syncthreads();
    }
    if (threadIdx.x == 0) {
        double cnt = 100.0 * H;
        double mean = r1[0] / cnt;
        double var = r2[0] / cnt - mean * mean;
        if (var < 0.0) var = 0.0;
        stat[2 * s] = (float)mean;
        stat[2 * s + 1] = (float)(1.0 / sqrt(var + 1e-5));
    }
}

__global__ void k_seg_apply(const float* __restrict__ y, const float* __restrict__ stat,
                            const float* __restrict__ g, const float* __restrict__ bb,
                            float* __restrict__ hout, int S, int H, int total) {
    int idx = blockIdx.x * blockDim.x + threadIdx.x;
    if (idx >= total) return;
    int c = idx % H;
    int rr = idx / H;
    int v = rr % Vv;
    int s = (rr / Vv) % S;
    int nm = rr / (Vv * S);
    int b = nm * Vv + v;
    float val = (y[((size_t)b * S + s) * H + c] - stat[2 * s]) * stat[2 * s + 1] * g[s] + bb[s];
    hout[idx] = val;
}

__global__ void k_final(const float* __restrict__ y2, const float* __restrict__ stat,
                        const float* __restrict__ g, const float* __restrict__ bb,
                        const float* __restrict__ fcW, const float* __restrict__ fcb,
                        float* __restrict__ out) {
    __shared__ float pooled[C2];
    int n = blockIdx.x;
    for (int o = threadIdx.x; o < C2; o += blockDim.x) {
        float acc = 0.f;
        for (int m = 0; m < 2; m++)
            for (int v = 0; v < Vv; v++) {
                int b = (n * 2 + m) * Vv + v;
                for (int s = 0; s < S2n; s++) {
                    float val = (y2[((size_t)b * S2n + s) * C2 + o] - stat[2 * s]) * stat[2 * s + 1] * g[s] + bb[s];
                    acc += val;
                }
            }
        pooled[o] = acc / (2.f * Vv * S2n);
    }
    __syncthreads();
    for (int cls = threadIdx.x; cls < NCLS; cls += blockDim.x) {
        float acc = fcb[cls];
        for (int o = 0; o < C2; o++) acc += pooled[o] * fcW[cls * C2 + o];
        out[n * NCLS + cls] = acc;
    }
}

// ======================= host =======================

static void make_segs(int T, int S, Seg& seg, int& L) {
    double delta = (double)(T - 1) / (double)S;
    int tv[65];
    for (int i = 0; i <= S; i++) {
        double v = 1.0 + delta * (double)i;
        tv[i] = (int)nearbyint(v);
    }
    tv[S] = T;
    L = 0;
    for (int s = 0; s < S; s++) {
        seg.starts[s] = tv[s] - 1;
        seg.ends[s] = tv[s + 1] - 1;
        int len = seg.ends[s] - seg.starts[s] + 1;
        if (len > L) L = len;
    }
    if (L > 4) L = 4;
}

extern "C" void kernel_launch(void* const* d_in, const int* in_sizes, int n_in,
                              void* d_out, int out_size) {
    (void)in_sizes; (void)n_in; (void)out_size;
    const float* x        = (const float*)d_in[0];
    const float* dbn_g    = (const float*)d_in[2];
    const float* dbn_b    = (const float*)d_in[3];
    const float* Ap1      = (const float*)d_in[4];
    const float* Ar1      = (const float*)d_in[5];
    const float* W1       = (const float*)d_in[6];
    const float* b1       = (const float*)d_in[7];
    const float* bn1_g    = (const float*)d_in[8];
    const float* bn1_b    = (const float*)d_in[9];
    const float* Wih1     = (const float*)d_in[10];
    const float* Whh1     = (const float*)d_in[11];
    const float* bih1     = (const float*)d_in[12];
    const float* bhh1     = (const float*)d_in[13];
    const float* bs1_g    = (const float*)d_in[14];
    const float* bs1_b    = (const float*)d_in[15];
    const float* Ap2      = (const float*)d_in[16];
    const float* Ar2      = (const float*)d_in[17];
    const float* W2       = (const float*)d_in[18];
    const float* b2       = (const float*)d_in[19];
    const float* bn2_g    = (const float*)d_in[20];
    const float* bn2_b    = (const float*)d_in[21];
    const float* Wih2     = (const float*)d_in[22];
    const float* Whh2     = (const float*)d_in[23];
    const float* bih2     = (const float*)d_in[24];
    const float* bhh2     = (const float*)d_in[25];
    const float* bs2_g    = (const float*)d_in[26];
    const float* bs2_b    = (const float*)d_in[27];
    const float* fcW      = (const float*)d_in[28];
    const float* fcb      = (const float*)d_in[29];
    float* out = (float*)d_out;

    float *p_h0, *p_stat0, *p_S1, *p_O1, *p_stat1, *p_seq1, *p_xp1, *p_WT1, *p_y1,
          *p_ss1, *p_h1b, *p_O2, *p_stat2, *p_seq2, *p_xp2, *p_WT2, *p_y2, *p_ss2;
    __half *p_f1h, *p_f2h, *p_W1h_hi, *p_W1h_lo, *p_W2ih_hi, *p_W2ih_lo;
    __nv_bfloat16 *p_W2hi, *p_W2lo, *p_S2hi, *p_S2lo;
    cudaGetSymbolAddress((void**)&p_h0, g_h0);
    cudaGetSymbolAddress((void**)&p_stat0, g_stat0);
    cudaGetSymbolAddress((void**)&p_S1, g_S1);
    cudaGetSymbolAddress((void**)&p_O1, g_O1);
    cudaGetSymbolAddress((void**)&p_stat1, g_stat1);
    cudaGetSymbolAddress((void**)&p_seq1, g_seq1);
    cudaGetSymbolAddress((void**)&p_xp1, g_xp1);
    cudaGetSymbolAddress((void**)&p_WT1, g_WT1);
    cudaGetSymbolAddress((void**)&p_y1, g_y1);
    cudaGetSymbolAddress((void**)&p_ss1, g_sstat1);
    cudaGetSymbolAddress((void**)&p_h1b, g_h1b);
    cudaGetSymbolAddress((void**)&p_O2, g_O2);
    cudaGetSymbolAddress((void**)&p_stat2, g_stat2);
    cudaGetSymbolAddress((void**)&p_seq2, g_seq2);
    cudaGetSymbolAddress((void**)&p_xp2, g_xp2);
    cudaGetSymbolAddress((void**)&p_WT2, g_WT2);
    cudaGetSymbolAddress((void**)&p_y2, g_y2);
    cudaGetSymbolAddress((void**)&p_ss2, g_sstat2);
    cudaGetSymbolAddress((void**)&p_f1h, g_f1h);
    cudaGetSymbolAddress((void**)&p_f2h, g_f2h);
    cudaGetSymbolAddress((void**)&p_W1h_hi, g_W1h_hi);
    cudaGetSymbolAddress((void**)&p_W1h_lo, g_W1h_lo);
    cudaGetSymbolAddress((void**)&p_W2ih_hi, g_W2ih_hi);
    cudaGetSymbolAddress((void**)&p_W2ih_lo, g_W2ih_lo);
    cudaGetSymbolAddress((void**)&p_W2hi, g_W2hi);
    cudaGetSymbolAddress((void**)&p_W2lo, g_W2lo);
    cudaGetSymbolAddress((void**)&p_S2hi, g_S2hi);
    cudaGetSymbolAddress((void**)&p_S2lo, g_S2lo);

    Seg seg1, seg2; int L1, L2;
    make_segs(Tt, S1n, seg1, L1);
    make_segs(S1n, S2n, seg2, L2);

    // weight prep
    k_transpose<<<(4 * C1 * C1 + 255) / 256, 256>>>(Whh1, p_WT1, 4 * C1, C1);
    k_transpose<<<(4 * C2 * C2 + 255) / 256, 256>>>(Whh2, p_WT2, 4 * C2, C2);
    k_cvt_f16split<<<(384 * KP1 + 255) / 256, 256>>>(Wih1, p_W1h_hi, p_W1h_lo, 384, IN1, KP1);
    k_cvt_f16split_v4<<<((768 * IN2 / 4) + 255) / 256, 256>>>(
        (const float4*)Wih2, (uint2*)p_W2ih_hi, (uint2*)p_W2ih_lo, 768 * IN2 / 4);
    k_cvt_bfsplit<<<(192 * KG2 + 255) / 256, 256>>>(W2, p_W2hi, p_W2lo, 192 * KG2);

    // ---- data BN ----
    k_bn0_stats<<<150, 256>>>(x, p_stat0);
    k_bn0_apply<<<(NM * Tt * Vv * Cin + 255) / 256, 256>>>(x, p_stat0, dbn_g, dbn_b, p_h0);

    // ---- GCN 1 (fp32) ----
    k_gcn_support<<<NM * Tt, 256, Vv * Cin * sizeof(float)>>>(p_h0, Ap1, Ar1, p_S1, Tt, Cin);
    {
        dim3 grid((C1 + TBN - 1) / TBN, (NM * Tt * Vv + TBM - 1) / TBM);
        k_gemm_abt<<<grid, 256>>>(p_S1, W1, b1, p_O1, NM * Tt * Vv, C1, Kk * Cin);
    }
    k_colstats<<<C1, 256>>>(p_O1, p_stat1, NM * Tt * Vv, C1);
    k_bn_relu_seq<<<(NM * Tt * Vv * C1 + 255) / 256, 256>>>(p_O1, p_stat1, bn1_g, bn1_b, p_seq1, Tt, C1, NM * Tt * Vv * C1);

    // ---- logsig + LSTM 1 ----
    k_feats_f16_v2<<<100 * S1n, 256, 2 * C1 * sizeof(float)>>>(p_seq1, p_f1h, Tt, C1, S1n, IN1, KP1, seg1);
    {
        int smem = GF_STAGES * (128 * GF_LDA + 2 * 128 * GF_LDA) * (int)sizeof(__half);
        cudaFuncSetAttribute(k_gemm_f16, cudaFuncAttributeMaxDynamicSharedMemorySize, smem);
        dim3 grid(384 / 128, (5000 + 127) / 128);
        k_gemm_f16<<<grid, 256, smem>>>(p_f1h, p_W1h_hi, p_W1h_lo, bih1, bhh1, p_xp1, 5000, 384, KP1);
    }
    int smem1 = (6 * C1 + C1 * 4 * C1) * (int)sizeof(float);
    cudaFuncSetAttribute(k_lstm, cudaFuncAttributeMaxDynamicSharedMemorySize, smem1);
    k_lstm<<<100, 4 * C1, smem1>>>(p_xp1, p_WT1, p_y1, S1n, C1, 1);
    k_seg_stats<<<S1n, 256>>>(p_y1, p_ss1, S1n, C1);
    k_seg_apply<<<(NM * S1n * Vv * C1 + 255) / 256, 256>>>(p_y1, p_ss1, bs1_g, bs1_b, p_h1b, S1n, C1, NM * S1n * Vv * C1);

    // ---- GCN 2 (bf16 3-pass tensor path) ----
    k_gcn_support_bf<<<NM * S1n, 256, Vv * C1 * sizeof(float)>>>(p_h1b, Ap2, Ar2, p_S2hi, p_S2lo, S1n, C1);
    {
        dim3 grid(192 / 64, (5000 + 63) / 64);
        k_mma_gemm_bf<<<grid, 128>>>(p_S2hi, p_S2lo, p_W2hi, p_W2lo, b2, p_O2, 5000, 192, KG2);
    }
    k_colstats<<<C2, 256>>>(p_O2, p_stat2, NM * S1n * Vv, C2);
    k_bn_relu_seq<<<(NM * S1n * Vv * C2 + 255) / 256, 256>>>(p_O2, p_stat2, bn2_g, bn2_b, p_seq2, S1n, C2, NM * S1n * Vv * C2);

    // ---- logsig + LSTM 2 ----
    k_feats_f16_v2<<<100 * S2n, 256, 2 * C2 * sizeof(float)>>>(p_seq2, p_f2h, S1n, C2, S2n, IN2, IN2, seg2);
    {
        int smem = GF_STAGES * (128 * GF_LDA + 2 * 128 * GF_LDA) * (int)sizeof(__half);
        dim3 grid(768 / 128, (3000 + 127) / 128);
        k_gemm_f16<<<grid, 256, smem>>>(p_f2h, p_W2ih_hi, p_W2ih_lo, bih2, bhh2, p_xp2, 3000, 768, IN2);
    }
    int smem2 = 6 * C2 * (int)sizeof(float);
    k_lstm<<<100, 4 * C2, smem2>>>(p_xp2, p_WT2, p_y2, S2n, C2, 0);
    k_seg_stats<<<S2n, 256>>>(p_y2, p_ss2, S2n, C2);

    // ---- pooling + fc ----
    k_final<<<Nn, 256>>>(p_y2, p_ss2, bs2_g, bs2_b, fcW, fcb, out);
}

// round 5
// speedup vs baseline: 5.0198x; 1.0432x over previous
#include <cuda_runtime.h>
#include <cuda_bf16.h>
#include <cuda_fp16.h>
#include <cmath>
#include <cstdint>

// ======================= model constants =======================
#define Nn    2
#define Mm_   2
#define NM    4
#define Cin   3
#define Tt    100
#define Vv    25
#define Kk    13
#define C1    96
#define C2    192
#define S1n   50
#define S2n   30
#define IN1   4752     // 2*96 + 4560
#define IN2   18720    // 2*192 + 18336
#define KP1   4768     // IN1 padded to /32
#define KG2   1248     // 13*96
#define NCLS  60

struct Seg { int starts[64]; int ends[64]; };

// ======================= device scratch ========================
__device__ float g_h0[NM*Tt*Vv*Cin];
__device__ float g_stat0[150*2];
__device__ float g_S1[NM*Tt*Vv*Kk*Cin];
__device__ float g_O1[NM*Tt*Vv*C1];
__device__ float g_stat1[C1*2];
__device__ float g_seq1[100*Tt*C1];
__device__ float g_xp1[5000*4*C1];
__device__ float g_WT1[C1*4*C1];
__device__ float g_y1[100*S1n*C1];
__device__ float g_sstat1[S1n*2];
__device__ float g_h1b[NM*S1n*Vv*C1];
__device__ float g_O2[NM*S1n*Vv*C2];
__device__ float g_stat2[C2*2];
__device__ float g_seq2[100*S1n*C2];
__device__ float g_xp2[3000*4*C2];
__device__ float g_WT2[C2*4*C2];
__device__ float g_y2[100*S2n*C2];
__device__ float g_sstat2[S2n*2];

// f16 operands for the two big xp GEMMs (single-pass A and B)
__device__ __half g_f1h[5000*KP1];
__device__ __half g_f2h[3000*IN2];
__device__ __half g_W1h[384*KP1];
__device__ __half g_W2ih[768*IN2];

// bf16 hi/lo operands for gcn2 GEMM (3-pass)
__device__ __nv_bfloat16 g_W2hi[192*KG2],  g_W2lo[192*KG2];
__device__ __nv_bfloat16 g_S2hi[5000*KG2], g_S2lo[5000*KG2];

// ======================= helpers ===============================

__device__ __forceinline__ void st_split_bf(__nv_bfloat16* hi, __nv_bfloat16* lo, size_t i, float v) {
    __nv_bfloat16 h = __float2bfloat16(v);
    hi[i] = h;
    lo[i] = __float2bfloat16(v - __bfloat162float(h));
}

__device__ __forceinline__ void cp_async16(void* smem, const void* gmem) {
    uint32_t s = (uint32_t)__cvta_generic_to_shared(smem);
    asm volatile("cp.async.cg.shared.global [%0], [%1], 16;\n" :: "r"(s), "l"(gmem));
}
#define CP_COMMIT() asm volatile("cp.async.commit_group;\n" ::: "memory")
#define CP_WAIT1()  asm volatile("cp.async.wait_group 1;\n" ::: "memory")

__device__ __forceinline__ void mma16816_bf(float* d, const uint32_t* a, const uint32_t* b) {
    asm volatile(
        "mma.sync.aligned.m16n8k16.row.col.f32.bf16.bf16.f32 "
        "{%0,%1,%2,%3}, {%4,%5,%6,%7}, {%8,%9}, {%0,%1,%2,%3};"
        : "+f"(d[0]), "+f"(d[1]), "+f"(d[2]), "+f"(d[3])
        : "r"(a[0]), "r"(a[1]), "r"(a[2]), "r"(a[3]), "r"(b[0]), "r"(b[1]));
}

__device__ __forceinline__ void mma16816_f16(float* d, const uint32_t* a, uint32_t b0, uint32_t b1) {
    asm volatile(
        "mma.sync.aligned.m16n8k16.row.col.f32.f16.f16.f32 "
        "{%0,%1,%2,%3}, {%4,%5,%6,%7}, {%8,%9}, {%0,%1,%2,%3};"
        : "+f"(d[0]), "+f"(d[1]), "+f"(d[2]), "+f"(d[3])
        : "r"(a[0]), "r"(a[1]), "r"(a[2]), "r"(a[3]), "r"(b0), "r"(b1));
}

#define LDSM4(r0, r1, r2, r3, addr) \
    asm volatile("ldmatrix.sync.aligned.m8n8.x4.shared.b16 {%0,%1,%2,%3}, [%4];" \
        : "=r"(r0), "=r"(r1), "=r"(r2), "=r"(r3) : "r"(addr))

// ======================= small kernels =========================

__global__ void k_transpose(const float* __restrict__ W, float* __restrict__ WT, int G, int H) {
    int idx = blockIdx.x * blockDim.x + threadIdx.x;
    if (idx < G * H) {
        int j = idx / H, k = idx % H;
        WT[k * G + j] = W[j * H + k];
    }
}

// fp32 (N,K) -> f16 (N,Kpad), zero tail
__global__ void k_cvt_f16_pad(const float* __restrict__ W, __half* __restrict__ hi,
                              int Nrows, int K, int Kpad) {
    int idx = blockIdx.x * blockDim.x + threadIdx.x;
    if (idx >= Nrows * Kpad) return;
    int n = idx / Kpad, k = idx % Kpad;
    float v = (k < K) ? W[(size_t)n * K + k] : 0.f;
    hi[idx] = __float2half_rn(v);
}

// vectorized f16 convert, Kpad == K, total % 4 == 0
__global__ void k_cvt_f16_v4(const float4* __restrict__ W, uint2* __restrict__ hi, int total4) {
    int idx = blockIdx.x * blockDim.x + threadIdx.x;
    if (idx >= total4) return;
    float4 v = W[idx];
    __half h0 = __float2half_rn(v.x), h1 = __float2half_rn(v.y);
    __half h2 = __float2half_rn(v.z), h3 = __float2half_rn(v.w);
    uint2 ho;
    ho.x = (uint32_t)__half_as_ushort(h0) | ((uint32_t)__half_as_ushort(h1) << 16);
    ho.y = (uint32_t)__half_as_ushort(h2) | ((uint32_t)__half_as_ushort(h3) << 16);
    hi[idx] = ho;
}

// fp32 -> bf16 hi/lo
__global__ void k_cvt_bfsplit(const float* __restrict__ W, __nv_bfloat16* __restrict__ hi,
                              __nv_bfloat16* __restrict__ lo, int total) {
    int idx = blockIdx.x * blockDim.x + threadIdx.x;
    if (idx >= total) return;
    st_split_bf(hi, lo, idx, W[idx]);
}

__global__ void k_bn0_stats(const float* __restrict__ x, float* __restrict__ stat) {
    int ch = blockIdx.x;
    int m = ch / (Vv * Cin);
    int v = (ch / Cin) % Vv;
    int c = ch % Cin;
    double s = 0.0, ss = 0.0;
    for (int i = threadIdx.x; i < Nn * Tt; i += blockDim.x) {
        int n = i / Tt, t = i % Tt;
        float val = x[(((n * Cin + c) * Tt + t) * Vv + v) * Mm_ + m];
        s += val; ss += (double)val * val;
    }
    __shared__ double r1[256], r2[256];
    r1[threadIdx.x] = s; r2[threadIdx.x] = ss;
    __syncthreads();
    for (int off = 128; off > 0; off >>= 1) {
        if (threadIdx.x < off) { r1[threadIdx.x] += r1[threadIdx.x + off]; r2[threadIdx.x] += r2[threadIdx.x + off]; }
        __syncthreads();
    }
    if (threadIdx.x == 0) {
        double cnt = (double)(Nn * Tt);
        double mean = r1[0] / cnt;
        double var = r2[0] / cnt - mean * mean;
        if (var < 0.0) var = 0.0;
        stat[2 * ch] = (float)mean;
        stat[2 * ch + 1] = (float)(1.0 / sqrt(var + 1e-5));
    }
}

__global__ void k_bn0_apply(const float* __restrict__ x, const float* __restrict__ stat,
                            const float* __restrict__ g, const float* __restrict__ b,
                            float* __restrict__ h0) {
    int idx = blockIdx.x * blockDim.x + threadIdx.x;
    if (idx >= NM * Tt * Vv * Cin) return;
    int c = idx % Cin;
    int v = (idx / Cin) % Vv;
    int t = (idx / (Cin * Vv)) % Tt;
    int nm = idx / (Cin * Vv * Tt);
    int n = nm >> 1, m = nm & 1;
    int ch = m * (Vv * Cin) + v * Cin + c;
    float val = x[(((n * Cin + c) * Tt + t) * Vv + v) * Mm_ + m];
    h0[idx] = (val - stat[2 * ch]) * stat[2 * ch + 1] * g[ch] + b[ch];
}

// fp32 support (layer 1)
__global__ void k_gcn_support(const float* __restrict__ hin, const float* __restrict__ Ap,
                              const float* __restrict__ Ares, float* __restrict__ Sout,
                              int T, int Cc) {
    __shared__ float Asm[325 * 25];
    extern __shared__ float hsm[];
    int blk = blockIdx.x;
    for (int i = threadIdx.x; i < 325 * 25; i += blockDim.x) Asm[i] = Ap[i] + Ares[i];
    const float* hrow = hin + (size_t)blk * Vv * Cc;
    for (int i = threadIdx.x; i < Vv * Cc; i += blockDim.x) hsm[i] = hrow[i];
    __syncthreads();
    int tot = Vv * Kk * Cc;
    float* outrow = Sout + (size_t)blk * tot;
    for (int f = threadIdx.x; f < tot; f += blockDim.x) {
        int c = f % Cc;
        int k = (f / Cc) % Kk;
        int v = f / (Kk * Cc);
        const float* arow = Asm + (k * Vv + v) * Vv;
        float acc = 0.f;
        #pragma unroll
        for (int u = 0; u < Vv; u++) acc += arow[u] * hsm[u * Cc + c];
        outrow[f] = acc;
    }
}

// bf16 hi/lo support (layer 2)
__global__ void k_gcn_support_bf(const float* __restrict__ hin, const float* __restrict__ Ap,
                                 const float* __restrict__ Ares, __nv_bfloat16* __restrict__ Shi,
                                 __nv_bfloat16* __restrict__ Slo, int T, int Cc) {
    __shared__ float Asm[325 * 25];
    extern __shared__ float hsm[];
    int blk = blockIdx.x;
    for (int i = threadIdx.x; i < 325 * 25; i += blockDim.x) Asm[i] = Ap[i] + Ares[i];
    const float* hrow = hin + (size_t)blk * Vv * Cc;
    for (int i = threadIdx.x; i < Vv * Cc; i += blockDim.x) hsm[i] = hrow[i];
    __syncthreads();
    int tot = Vv * Kk * Cc;
    size_t base = (size_t)blk * tot;
    for (int f = threadIdx.x; f < tot; f += blockDim.x) {
        int c = f % Cc;
        int k = (f / Cc) % Kk;
        int v = f / (Kk * Cc);
        const float* arow = Asm + (k * Vv + v) * Vv;
        float acc = 0.f;
        #pragma unroll
        for (int u = 0; u < Vv; u++) acc += arow[u] * hsm[u * Cc + c];
        st_split_bf(Shi, Slo, base + f, acc);
    }
}

// fp32 GEMM (gcn1 only)
#define TBM 64
#define TBN 64
#define TBK 16
__global__ void k_gemm_abt(const float* __restrict__ A, const float* __restrict__ B,
                           const float* __restrict__ bias1,
                           float* __restrict__ C, int M, int N, int K) {
    __shared__ float As[TBK][TBM];
    __shared__ float Bs[TBK][TBN];
    int m0 = blockIdx.y * TBM;
    int n0 = blockIdx.x * TBN;
    int tid = threadIdx.x;
    int tx = tid & 15, ty = tid >> 4;
    float acc[4][4] = {};
    for (int kt = 0; kt < K; kt += TBK) {
        #pragma unroll
        for (int e = 0; e < 4; e++) {
            int idx = tid + e * 256;
            int r = idx >> 4, c = idx & 15;
            int gk = kt + c;
            int gm = m0 + r;
            As[c][r] = (gm < M && gk < K) ? A[(size_t)gm * K + gk] : 0.f;
            int gn = n0 + r;
            Bs[c][r] = (gn < N && gk < K) ? B[(size_t)gn * K + gk] : 0.f;
        }
        __syncthreads();
        #pragma unroll
        for (int kk = 0; kk < TBK; kk++) {
            float4 a4 = *reinterpret_cast<const float4*>(&As[kk][ty * 4]);
            float4 b4 = *reinterpret_cast<const float4*>(&Bs[kk][tx * 4]);
            float av[4] = {a4.x, a4.y, a4.z, a4.w};
            float bv[4] = {b4.x, b4.y, b4.z, b4.w};
            #pragma unroll
            for (int r = 0; r < 4; r++)
                #pragma unroll
                for (int c = 0; c < 4; c++) acc[r][c] += av[r] * bv[c];
        }
        __syncthreads();
    }
    #pragma unroll
    for (int r = 0; r < 4; r++) {
        int gm = m0 + ty * 4 + r;
        if (gm >= M) continue;
        #pragma unroll
        for (int c = 0; c < 4; c++) {
            int gn = n0 + tx * 4 + c;
            if (gn >= N) continue;
            C[(size_t)gm * N + gn] = acc[r][c] + (bias1 ? bias1[gn] : 0.f);
        }
    }
}

// ====== bf16 3-pass tensor GEMM (gcn2): 64x64 tile, 128 thr ======
__global__ void __launch_bounds__(128) k_mma_gemm_bf(
    const __nv_bfloat16* __restrict__ Ahi, const __nv_bfloat16* __restrict__ Alo,
    const __nv_bfloat16* __restrict__ Bhi, const __nv_bfloat16* __restrict__ Blo,
    const float* __restrict__ bias1,
    float* __restrict__ C, int M, int N, int K)
{
    __shared__ __nv_bfloat16 sA[2][2][64][40];
    __shared__ __nv_bfloat16 sB[2][2][64][40];
    const int m0 = blockIdx.y * 64, n0 = blockIdx.x * 64;
    const int tid = threadIdx.x;
    const int lane = tid & 31, warp = tid >> 5;
    const int wm = (warp & 1) * 32, wn = (warp >> 1) * 32;
    const int r = lane >> 2, s2 = (lane & 3) * 2;
    float acc[2][4][4];
    #pragma unroll
    for (int a = 0; a < 2; a++)
        #pragma unroll
        for (int b = 0; b < 4; b++)
            #pragma unroll
            for (int c = 0; c < 4; c++) acc[a][b][c] = 0.f;

    const int srow = tid >> 2;
    const int schk = (tid & 3) * 8;
    const int nk = K >> 5;

    #pragma unroll
    for (int h = 0; h < 2; h++) {
        int row = srow + h * 32;
        int ga = m0 + row; if (ga >= M) ga = M - 1;
        int gb = n0 + row; if (gb >= N) gb = N - 1;
        cp_async16(&sA[0][0][row][schk], Ahi + (size_t)ga * K + schk);
        cp_async16(&sA[0][1][row][schk], Alo + (size_t)ga * K + schk);
        cp_async16(&sB[0][0][row][schk], Bhi + (size_t)gb * K + schk);
        cp_async16(&sB[0][1][row][schk], Blo + (size_t)gb * K + schk);
    }
    CP_COMMIT();

    for (int kc = 0; kc < nk; kc++) {
        int st = kc & 1;
        if (kc + 1 < nk) {
            int kt = (kc + 1) << 5;
            int sn = st ^ 1;
            #pragma unroll
            for (int h = 0; h < 2; h++) {
                int row = srow + h * 32;
                int ga = m0 + row; if (ga >= M) ga = M - 1;
                int gb = n0 + row; if (gb >= N) gb = N - 1;
                cp_async16(&sA[sn][0][row][schk], Ahi + (size_t)ga * K + kt + schk);
                cp_async16(&sA[sn][1][row][schk], Alo + (size_t)ga * K + kt + schk);
                cp_async16(&sB[sn][0][row][schk], Bhi + (size_t)gb * K + kt + schk);
                cp_async16(&sB[sn][1][row][schk], Blo + (size_t)gb * K + kt + schk);
            }
        }
        CP_COMMIT();
        CP_WAIT1();
        __syncthreads();

        #pragma unroll
        for (int ks = 0; ks < 2; ks++) {
            const int kb = ks * 16 + s2;
            uint32_t ah[2][4], al[2][4];
            #pragma unroll
            for (int mt = 0; mt < 2; mt++) {
                int row = wm + mt * 16 + r;
                const __nv_bfloat16* p0 = &sA[st][0][row][kb];
                const __nv_bfloat16* p1 = &sA[st][0][row + 8][kb];
                ah[mt][0] = *(const uint32_t*)p0;
                ah[mt][1] = *(const uint32_t*)p1;
                ah[mt][2] = *(const uint32_t*)(p0 + 8);
                ah[mt][3] = *(const uint32_t*)(p1 + 8);
                const __nv_bfloat16* q0 = &sA[st][1][row][kb];
                const __nv_bfloat16* q1 = &sA[st][1][row + 8][kb];
                al[mt][0] = *(const uint32_t*)q0;
                al[mt][1] = *(const uint32_t*)q1;
                al[mt][2] = *(const uint32_t*)(q0 + 8);
                al[mt][3] = *(const uint32_t*)(q1 + 8);
            }
            #pragma unroll
            for (int nt = 0; nt < 4; nt++) {
                int nrow = wn + nt * 8 + r;
                uint32_t bh[2], bl[2];
                const __nv_bfloat16* p = &sB[st][0][nrow][kb];
                bh[0] = *(const uint32_t*)p;
                bh[1] = *(const uint32_t*)(p + 8);
                const __nv_bfloat16* q = &sB[st][1][nrow][kb];
                bl[0] = *(const uint32_t*)q;
                bl[1] = *(const uint32_t*)(q + 8);
                #pragma unroll
                for (int mt = 0; mt < 2; mt++) {
                    mma16816_bf(acc[mt][nt], ah[mt], bh);
                    mma16816_bf(acc[mt][nt], ah[mt], bl);
                    mma16816_bf(acc[mt][nt], al[mt], bh);
                }
            }
        }
        __syncthreads();
    }

    #pragma unroll
    for (int mt = 0; mt < 2; mt++) {
        int gm = m0 + wm + mt * 16 + r;
        #pragma unroll
        for (int nt = 0; nt < 4; nt++) {
            int gn = n0 + wn + nt * 8 + s2;
            if (gn >= N) continue;
            float bv0 = bias1 ? bias1[gn] : 0.f;
            float bv1 = bias1 ? bias1[gn + 1] : 0.f;
            if (gm < M) {
                C[(size_t)gm * N + gn]     = acc[mt][nt][0] + bv0;
                C[(size_t)gm * N + gn + 1] = acc[mt][nt][1] + bv1;
            }
            if (gm + 8 < M) {
                C[(size_t)(gm + 8) * N + gn]     = acc[mt][nt][2] + bv0;
                C[(size_t)(gm + 8) * N + gn + 1] = acc[mt][nt][3] + bv1;
            }
        }
    }
}

// ====== f16 single-pass tensor GEMM (xp1/xp2): 128x128 tile, 256 thr, ldmatrix, 3-stage ======
#define GF_STAGES 3
#define GF_LDA 40
__global__ void __launch_bounds__(256) k_gemm_f16(
    const __half* __restrict__ A, const __half* __restrict__ B,
    const float* __restrict__ bias1, const float* __restrict__ bias2,
    float* __restrict__ C, int M, int N, int K)
{
    extern __shared__ __half smem[];
    __half* sA = smem;                              // [GF_STAGES][128][GF_LDA]
    __half* sB = smem + GF_STAGES * 128 * GF_LDA;   // [GF_STAGES][128][GF_LDA]

    const int m0 = blockIdx.y * 128, n0 = blockIdx.x * 128;
    const int tid = threadIdx.x;
    const int lane = tid & 31, warp = tid >> 5;
    const int wm = (warp & 1) * 64;
    const int wn = (warp >> 1) * 32;
    const int nk = K >> 5;

    const uint32_t sA_u = (uint32_t)__cvta_generic_to_shared(sA);
    const uint32_t sB_u = (uint32_t)__cvta_generic_to_shared(sB);

    const int lrow = lane & 15;
    const int lkh  = (lane >> 4) << 3;
    const int brow = ((lane >> 4) << 3) + (lane & 7);
    const int bkh  = ((lane >> 3) & 1) << 3;

    float acc[4][4][4];
    #pragma unroll
    for (int a = 0; a < 4; a++)
        #pragma unroll
        for (int b = 0; b < 4; b++)
            #pragma unroll
            for (int c = 0; c < 4; c++) acc[a][b][c] = 0.f;

    auto load_stage = [&](int st, int kt) {
        #pragma unroll
        for (int e = 0; e < 2; e++) {
            int i = tid + e * 256;
            int row = i >> 2, chk = (i & 3) << 3;
            int ga = m0 + row; if (ga >= M) ga = M - 1;
            cp_async16(&sA[(st * 128 + row) * GF_LDA + chk], A + (size_t)ga * K + kt + chk);
            int gb = n0 + row; if (gb >= N) gb = N - 1;
            cp_async16(&sB[(st * 128 + row) * GF_LDA + chk], B + (size_t)gb * K + kt + chk);
        }
    };

    load_stage(0, 0);
    CP_COMMIT();
    load_stage(1, 32);
    CP_COMMIT();

    for (int kc = 0; kc < nk; kc++) {
        int st = kc % GF_STAGES;
        CP_WAIT1();
        __syncthreads();
        if (kc + 2 < nk) {
            load_stage((kc + 2) % GF_STAGES, (kc + 2) << 5);
            CP_COMMIT();
        }

        #pragma unroll
        for (int ks = 0; ks < 2; ks++) {
            const int kb = ks * 16;
            uint32_t a[4][4];
            #pragma unroll
            for (int mt = 0; mt < 4; mt++) {
                uint32_t addr = sA_u + (((st * 128) + wm + mt * 16 + lrow) * GF_LDA + kb + lkh) * 2;
                LDSM4(a[mt][0], a[mt][1], a[mt][2], a[mt][3], addr);
            }
            #pragma unroll
            for (int g = 0; g < 2; g++) {
                uint32_t bh0, bh1, bh2, bh3;
                uint32_t addr_h = sB_u + (((st * 128) + wn + g * 16 + brow) * GF_LDA + kb + bkh) * 2;
                LDSM4(bh0, bh1, bh2, bh3, addr_h);
                #pragma unroll
                for (int mt = 0; mt < 4; mt++) {
                    mma16816_f16(acc[mt][2 * g],     a[mt], bh0, bh1);
                    mma16816_f16(acc[mt][2 * g + 1], a[mt], bh2, bh3);
                }
            }
        }
        __syncthreads();
    }

    const int r = lane >> 2, cp = (lane & 3) * 2;
    #pragma unroll
    for (int mt = 0; mt < 4; mt++) {
        int gm = m0 + wm + mt * 16 + r;
        #pragma unroll
        for (int nt = 0; nt < 4; nt++) {
            int gn = n0 + wn + nt * 8 + cp;
            float bv0 = 0.f, bv1 = 0.f;
            if (bias1) { bv0 += bias1[gn]; bv1 += bias1[gn + 1]; }
            if (bias2) { bv0 += bias2[gn]; bv1 += bias2[gn + 1]; }
            if (gm < M) {
                C[(size_t)gm * N + gn]     = acc[mt][nt][0] + bv0;
                C[(size_t)gm * N + gn + 1] = acc[mt][nt][1] + bv1;
            }
            if (gm + 8 < M) {
                C[(size_t)(gm + 8) * N + gn]     = acc[mt][nt][2] + bv0;
                C[(size_t)(gm + 8) * N + gn + 1] = acc[mt][nt][3] + bv1;
            }
        }
    }
}

// ======================= elementwise chain =====================

__global__ void k_colstats(const float* __restrict__ X, float* __restrict__ stat, int Mrows, int Ncols) {
    int col = blockIdx.x;
    double s = 0.0, ss = 0.0;
    for (int rr = threadIdx.x; rr < Mrows; rr += blockDim.x) {
        float v = X[(size_t)rr * Ncols + col];
        s += v; ss += (double)v * v;
    }
    __shared__ double r1[256], r2[256];
    r1[threadIdx.x] = s; r2[threadIdx.x] = ss;
    __syncthreads();
    for (int off = 128; off > 0; off >>= 1) {
        if (threadIdx.x < off) { r1[threadIdx.x] += r1[threadIdx.x + off]; r2[threadIdx.x] += r2[threadIdx.x + off]; }
        __syncthreads();
    }
    if (threadIdx.x == 0) {
        double cnt = (double)Mrows;
        double mean = r1[0] / cnt;
        double var = r2[0] / cnt - mean * mean;
        if (var < 0.0) var = 0.0;
        stat[2 * col] = (float)mean;
        stat[2 * col + 1] = (float)(1.0 / sqrt(var + 1e-5));
    }
}

__global__ void k_bn_relu_seq(const float* __restrict__ O, const float* __restrict__ stat,
                              const float* __restrict__ g, const float* __restrict__ bb,
                              float* __restrict__ seq, int T, int Cc, int total) {
    int idx = blockIdx.x * blockDim.x + threadIdx.x;
    if (idx >= total) return;
    int c = idx % Cc;
    int j = idx / Cc;
    int v = j % Vv;
    int t = (j / Vv) % T;
    int nm = j / (Vv * T);
    float val = (O[idx] - stat[2 * c]) * stat[2 * c + 1] * g[c] + bb[c];
    val = fmaxf(val, 0.f);
    int b = nm * Vv + v;
    seq[((size_t)b * T + t) * Cc + c] = val;
}

// closed-form log-sig feats -> f16: [p0, p2-p0, 0.5*(u_i w_j - u_j w_i)]
__global__ void k_feats_f16_v2(const float* __restrict__ seq, __half* __restrict__ f,
                               int T, int d, int S, int in_dim, int Kpad, Seg seg) {
    extern __shared__ float sm2[];    // su[d], w[d]
    float* s_su = sm2;
    float* s_w  = sm2 + d;
    int bs = blockIdx.x;
    int b = bs / S, s = bs % S;
    int st = seg.starts[s], en = seg.ends[s];
    int i1 = min(st + 1, en), i2 = min(st + 2, en);
    const float* x0 = seq + ((size_t)b * T + st) * d;
    const float* x1 = seq + ((size_t)b * T + i1) * d;
    const float* x2 = seq + ((size_t)b * T + i2) * d;
    __half* out = f + (size_t)bs * Kpad;
    int tid = threadIdx.x;
    for (int i = tid; i < d; i += blockDim.x) {
        float p0 = x0[i], p1 = x1[i], p2 = x2[i];
        s_su[i] = 0.5f * (p1 - p0);
        s_w[i]  = p2 - p1;
        out[i] = __float2half_rn(p0);
        out[d + i] = __float2half_rn(p2 - p0);
    }
    for (int i = in_dim + tid; i < Kpad; i += blockDim.x) out[i] = __ushort_as_half(0);
    __syncthreads();
    __half* lev = out + 2 * d;
    int npairs = in_dim - 2 * d;
    if (en - st < 2) {
        uint4 z4; z4.x = z4.y = z4.z = z4.w = 0u;
        uint4* o4 = (uint4*)lev;
        int n8 = npairs >> 3;
        for (int i = tid; i < n8; i += blockDim.x) o4[i] = z4;
        return;
    }
    int lane = tid & 31, wp = tid >> 5, nw = blockDim.x >> 5;
    for (int i = wp; i < d - 1; i += nw) {
        float sui = s_su[i], wi = s_w[i];
        __half* row = lev + (size_t)i * (2 * d - i - 1) / 2 - (i + 1);
        for (int j = i + 1 + lane; j < d; j += 32) {
            float v = fmaf(sui, s_w[j], -(wi * s_su[j]));
            row[j] = __float2half_rn(v);
        }
    }
}

__device__ __forceinline__ float sigf(float x) { return 1.f / (1.f + expf(-x)); }

// LSTM layer 1: H=96, G=384. 192 threads, 2 gates/thread, W staged in smem.
__global__ void __launch_bounds__(192) k_lstm1(const float* __restrict__ xp,
                                               const float* __restrict__ WT,
                                               float* __restrict__ y, int S) {
    extern __shared__ float sm[];
    float* sh = sm;            // 96
    float* sc = sm + 96;       // 96
    float* sg = sm + 192;      // 384
    float* sW = sm + 576;      // 96*384
    int b = blockIdx.x, tid = threadIdx.x;
    {
        const float4* Wv = (const float4*)WT;
        float4* sWv = (float4*)sW;
        for (int i = tid; i < 96 * 384 / 4; i += 192) sWv[i] = Wv[i];
    }
    if (tid < 96) { sh[tid] = 0.f; sc[tid] = 0.f; }
    __syncthreads();
    int j0 = 2 * tid;
    for (int s = 0; s < S; s++) {
        float2 xg = *(const float2*)&xp[((size_t)b * S + s) * 384 + j0];
        float g0 = xg.x, g1 = xg.y;
        #pragma unroll 8
        for (int k = 0; k < 96; k++) {
            float2 w = *(const float2*)&sW[k * 384 + j0];
            float hk = sh[k];
            g0 = fmaf(hk, w.x, g0);
            g1 = fmaf(hk, w.y, g1);
        }
        sg[j0] = g0; sg[j0 + 1] = g1;
        __syncthreads();
        if (tid < 96) {
            int j = tid;
            float iv = sigf(sg[j]);
            float fv = sigf(sg[96 + j]);
            float gv = tanhf(sg[192 + j]);
            float ov = sigf(sg[288 + j]);
            float cn = fv * sc[j] + iv * gv;
            sc[j] = cn;
            float hn = ov * tanhf(cn);
            sh[j] = hn;
            y[((size_t)b * S + s) * 96 + j] = hn;
        }
        __syncthreads();
    }
}

// LSTM layer 2: H=192, G=768. 192 threads, 4 gates/thread, 2 sequences/block, W from L2.
__global__ void __launch_bounds__(192) k_lstm2(const float* __restrict__ xp,
                                               const float* __restrict__ WT,
                                               float* __restrict__ y, int S) {
    __shared__ float2 sh2[192];       // (.x = seq a, .y = seq b)
    __shared__ float sc[2][192];
    __shared__ float sg[2][768];
    int b0 = blockIdx.x * 2, tid = threadIdx.x;
    if (tid < 192) { sh2[tid] = make_float2(0.f, 0.f); sc[0][tid] = 0.f; sc[1][tid] = 0.f; }
    __syncthreads();
    int j0 = 4 * tid;
    for (int s = 0; s < S; s++) {
        float4 xa = *(const float4*)&xp[((size_t)b0 * S + s) * 768 + j0];
        float4 xb = *(const float4*)&xp[((size_t)(b0 + 1) * S + s) * 768 + j0];
        float a0 = xa.x, a1 = xa.y, a2 = xa.z, a3 = xa.w;
        float c0 = xb.x, c1 = xb.y, c2 = xb.z, c3 = xb.w;
        #pragma unroll 4
        for (int k = 0; k < 192; k++) {
            float4 w = __ldg((const float4*)&WT[(size_t)k * 768 + j0]);
            float2 h = sh2[k];
            a0 = fmaf(h.x, w.x, a0); a1 = fmaf(h.x, w.y, a1);
            a2 = fmaf(h.x, w.z, a2); a3 = fmaf(h.x, w.w, a3);
            c0 = fmaf(h.y, w.x, c0); c1 = fmaf(h.y, w.y, c1);
            c2 = fmaf(h.y, w.z, c2); c3 = fmaf(h.y, w.w, c3);
        }
        *(float4*)&sg[0][j0] = make_float4(a0, a1, a2, a3);
        *(float4*)&sg[1][j0] = make_float4(c0, c1, c2, c3);
        __syncthreads();
        #pragma unroll
        for (int sq = 0; sq < 2; sq++) {
            int j = tid;
            float iv = sigf(sg[sq][j]);
            float fv = sigf(sg[sq][192 + j]);
            float gv = tanhf(sg[sq][384 + j]);
            float ov = sigf(sg[sq][576 + j]);
            float cn = fv * sc[sq][j] + iv * gv;
            sc[sq][j] = cn;
            float hn = ov * tanhf(cn);
            if (sq == 0) sh2[j].x = hn; else sh2[j].y = hn;
            y[((size_t)(b0 + sq) * S + s) * 192 + j] = hn;
        }
        __syncthreads();
    }
}

__global__ void k_seg_stats(const float* __restrict__ y, float* __restrict__ stat, int S, int H) {
    int s = blockIdx.x;
    double sum = 0.0, ssq = 0.0;
    for (int i = threadIdx.x; i < 100 * H; i += blockDim.x) {
        int b = i / H, h = i % H;
        float v = y[((size_t)b * S + s) * H + h];
        sum += v; ssq += (double)v * v;
    }
    __shared__ double r1[256], r2[256];
    r1[threadIdx.x] = sum; r2[threadIdx.x] = ssq;
    __syncthreads();
    for (int off = 128; off > 0; off >>= 1) {
        if (threadIdx.x < off) { r1[threadIdx.x] += r1[threadIdx.x + off]; r2[threadIdx.x] += r2[threadIdx.x + off]; }
        __syncthreads();
    }
    if (threadIdx.x == 0) {
        double cnt = 100.0 * H;
        double mean = r1[0] / cnt;
        double var = r2[0] / cnt - mean * mean;
        if (var < 0.0) var = 0.0;
        stat[2 * s] = (float)mean;
        stat[2 * s + 1] = (float)(1.0 / sqrt(var + 1e-5));
    }
}

__global__ void k_seg_apply(const float* __restrict__ y, const float* __restrict__ stat,
                            const float* __restrict__ g, const float* __restrict__ bb,
                            float* __restrict__ hout, int S, int H, int total) {
    int idx = blockIdx.x * blockDim.x + threadIdx.x;
    if (idx >= total) return;
    int c = idx % H;
    int rr = idx / H;
    int v = rr % Vv;
    int s = (rr / Vv) % S;
    int nm = rr / (Vv * S);
    int b = nm * Vv + v;
    float val = (y[((size_t)b * S + s) * H + c] - stat[2 * s]) * stat[2 * s + 1] * g[s] + bb[s];
    hout[idx] = val;
}

__global__ void k_final(const float* __restrict__ y2, const float* __restrict__ stat,
                        const float* __restrict__ g, const float* __restrict__ bb,
                        const float* __restrict__ fcW, const float* __restrict__ fcb,
                        float* __restrict__ out) {
    __shared__ float pooled[C2];
    int n = blockIdx.x;
    for (int o = threadIdx.x; o < C2; o += blockDim.x) {
        float acc = 0.f;
        for (int m = 0; m < 2; m++)
            for (int v = 0; v < Vv; v++) {
                int b = (n * 2 + m) * Vv + v;
                for (int s = 0; s < S2n; s++) {
                    float val = (y2[((size_t)b * S2n + s) * C2 + o] - stat[2 * s]) * stat[2 * s + 1] * g[s] + bb[s];
                    acc += val;
                }
            }
        pooled[o] = acc / (2.f * Vv * S2n);
    }
    __syncthreads();
    for (int cls = threadIdx.x; cls < NCLS; cls += blockDim.x) {
        float acc = fcb[cls];
        for (int o = 0; o < C2; o++) acc += pooled[o] * fcW[cls * C2 + o];
        out[n * NCLS + cls] = acc;
    }
}

// ======================= host =======================

static void make_segs(int T, int S, Seg& seg, int& L) {
    double delta = (double)(T - 1) / (double)S;
    int tv[65];
    for (int i = 0; i <= S; i++) {
        double v = 1.0 + delta * (double)i;
        tv[i] = (int)nearbyint(v);
    }
    tv[S] = T;
    L = 0;
    for (int s = 0; s < S; s++) {
        seg.starts[s] = tv[s] - 1;
        seg.ends[s] = tv[s + 1] - 1;
        int len = seg.ends[s] - seg.starts[s] + 1;
        if (len > L) L = len;
    }
    if (L > 4) L = 4;
}

extern "C" void kernel_launch(void* const* d_in, const int* in_sizes, int n_in,
                              void* d_out, int out_size) {
    (void)in_sizes; (void)n_in; (void)out_size;
    const float* x        = (const float*)d_in[0];
    const float* dbn_g    = (const float*)d_in[2];
    const float* dbn_b    = (const float*)d_in[3];
    const float* Ap1      = (const float*)d_in[4];
    const float* Ar1      = (const float*)d_in[5];
    const float* W1       = (const float*)d_in[6];
    const float* b1       = (const float*)d_in[7];
    const float* bn1_g    = (const float*)d_in[8];
    const float* bn1_b    = (const float*)d_in[9];
    const float* Wih1     = (const float*)d_in[10];
    const float* Whh1     = (const float*)d_in[11];
    const float* bih1     = (const float*)d_in[12];
    const float* bhh1     = (const float*)d_in[13];
    const float* bs1_g    = (const float*)d_in[14];
    const float* bs1_b    = (const float*)d_in[15];
    const float* Ap2      = (const float*)d_in[16];
    const float* Ar2      = (const float*)d_in[17];
    const float* W2       = (const float*)d_in[18];
    const float* b2       = (const float*)d_in[19];
    const float* bn2_g    = (const float*)d_in[20];
    const float* bn2_b    = (const float*)d_in[21];
    const float* Wih2     = (const float*)d_in[22];
    const float* Whh2     = (const float*)d_in[23];
    const float* bih2     = (const float*)d_in[24];
    const float* bhh2     = (const float*)d_in[25];
    const float* bs2_g    = (const float*)d_in[26];
    const float* bs2_b    = (const float*)d_in[27];
    const float* fcW      = (const float*)d_in[28];
    const float* fcb      = (const float*)d_in[29];
    float* out = (float*)d_out;

    float *p_h0, *p_stat0, *p_S1, *p_O1, *p_stat1, *p_seq1, *p_xp1, *p_WT1, *p_y1,
          *p_ss1, *p_h1b, *p_O2, *p_stat2, *p_seq2, *p_xp2, *p_WT2, *p_y2, *p_ss2;
    __half *p_f1h, *p_f2h, *p_W1h, *p_W2ih;
    __nv_bfloat16 *p_W2hi, *p_W2lo, *p_S2hi, *p_S2lo;
    cudaGetSymbolAddress((void**)&p_h0, g_h0);
    cudaGetSymbolAddress((void**)&p_stat0, g_stat0);
    cudaGetSymbolAddress((void**)&p_S1, g_S1);
    cudaGetSymbolAddress((void**)&p_O1, g_O1);
    cudaGetSymbolAddress((void**)&p_stat1, g_stat1);
    cudaGetSymbolAddress((void**)&p_seq1, g_seq1);
    cudaGetSymbolAddress((void**)&p_xp1, g_xp1);
    cudaGetSymbolAddress((void**)&p_WT1, g_WT1);
    cudaGetSymbolAddress((void**)&p_y1, g_y1);
    cudaGetSymbolAddress((void**)&p_ss1, g_sstat1);
    cudaGetSymbolAddress((void**)&p_h1b, g_h1b);
    cudaGetSymbolAddress((void**)&p_O2, g_O2);
    cudaGetSymbolAddress((void**)&p_stat2, g_stat2);
    cudaGetSymbolAddress((void**)&p_seq2, g_seq2);
    cudaGetSymbolAddress((void**)&p_xp2, g_xp2);
    cudaGetSymbolAddress((void**)&p_WT2, g_WT2);
    cudaGetSymbolAddress((void**)&p_y2, g_y2);
    cudaGetSymbolAddress((void**)&p_ss2, g_sstat2);
    cudaGetSymbolAddress((void**)&p_f1h, g_f1h);
    cudaGetSymbolAddress((void**)&p_f2h, g_f2h);
    cudaGetSymbolAddress((void**)&p_W1h, g_W1h);
    cudaGetSymbolAddress((void**)&p_W2ih, g_W2ih);
    cudaGetSymbolAddress((void**)&p_W2hi, g_W2hi);
    cudaGetSymbolAddress((void**)&p_W2lo, g_W2lo);
    cudaGetSymbolAddress((void**)&p_S2hi, g_S2hi);
    cudaGetSymbolAddress((void**)&p_S2lo, g_S2lo);

    Seg seg1, seg2; int L1, L2;
    make_segs(Tt, S1n, seg1, L1);
    make_segs(S1n, S2n, seg2, L2);

    // weight prep
    k_transpose<<<(4 * C1 * C1 + 255) / 256, 256>>>(Whh1, p_WT1, 4 * C1, C1);
    k_transpose<<<(4 * C2 * C2 + 255) / 256, 256>>>(Whh2, p_WT2, 4 * C2, C2);
    k_cvt_f16_pad<<<(384 * KP1 + 255) / 256, 256>>>(Wih1, p_W1h, 384, IN1, KP1);
    k_cvt_f16_v4<<<((768 * IN2 / 4) + 255) / 256, 256>>>(
        (const float4*)Wih2, (uint2*)p_W2ih, 768 * IN2 / 4);
    k_cvt_bfsplit<<<(192 * KG2 + 255) / 256, 256>>>(W2, p_W2hi, p_W2lo, 192 * KG2);

    // ---- data BN ----
    k_bn0_stats<<<150, 256>>>(x, p_stat0);
    k_bn0_apply<<<(NM * Tt * Vv * Cin + 255) / 256, 256>>>(x, p_stat0, dbn_g, dbn_b, p_h0);

    // ---- GCN 1 (fp32) ----
    k_gcn_support<<<NM * Tt, 256, Vv * Cin * sizeof(float)>>>(p_h0, Ap1, Ar1, p_S1, Tt, Cin);
    {
        dim3 grid((C1 + TBN - 1) / TBN, (NM * Tt * Vv + TBM - 1) / TBM);
        k_gemm_abt<<<grid, 256>>>(p_S1, W1, b1, p_O1, NM * Tt * Vv, C1, Kk * Cin);
    }
    k_colstats<<<C1, 256>>>(p_O1, p_stat1, NM * Tt * Vv, C1);
    k_bn_relu_seq<<<(NM * Tt * Vv * C1 + 255) / 256, 256>>>(p_O1, p_stat1, bn1_g, bn1_b, p_seq1, Tt, C1, NM * Tt * Vv * C1);

    // ---- logsig + LSTM 1 ----
    k_feats_f16_v2<<<100 * S1n, 256, 2 * C1 * sizeof(float)>>>(p_seq1, p_f1h, Tt, C1, S1n, IN1, KP1, seg1);
    {
        int smem = GF_STAGES * 2 * 128 * GF_LDA * (int)sizeof(__half);
        cudaFuncSetAttribute(k_gemm_f16, cudaFuncAttributeMaxDynamicSharedMemorySize, smem);
        dim3 grid(384 / 128, (5000 + 127) / 128);
        k_gemm_f16<<<grid, 256, smem>>>(p_f1h, p_W1h, bih1, bhh1, p_xp1, 5000, 384, KP1);
    }
    {
        int smem1 = (576 + 96 * 384) * (int)sizeof(float);
        cudaFuncSetAttribute(k_lstm1, cudaFuncAttributeMaxDynamicSharedMemorySize, smem1);
        k_lstm1<<<100, 192, smem1>>>(p_xp1, p_WT1, p_y1, S1n);
    }
    k_seg_stats<<<S1n, 256>>>(p_y1, p_ss1, S1n, C1);
    k_seg_apply<<<(NM * S1n * Vv * C1 + 255) / 256, 256>>>(p_y1, p_ss1, bs1_g, bs1_b, p_h1b, S1n, C1, NM * S1n * Vv * C1);

    // ---- GCN 2 (bf16 3-pass tensor path) ----
    k_gcn_support_bf<<<NM * S1n, 256, Vv * C1 * sizeof(float)>>>(p_h1b, Ap2, Ar2, p_S2hi, p_S2lo, S1n, C1);
    {
        dim3 grid(192 / 64, (5000 + 63) / 64);
        k_mma_gemm_bf<<<grid, 128>>>(p_S2hi, p_S2lo, p_W2hi, p_W2lo, b2, p_O2, 5000, 192, KG2);
    }
    k_colstats<<<C2, 256>>>(p_O2, p_stat2, NM * S1n * Vv, C2);
    k_bn_relu_seq<<<(NM * S1n * Vv * C2 + 255) / 256, 256>>>(p_O2, p_stat2, bn2_g, bn2_b, p_seq2, S1n, C2, NM * S1n * Vv * C2);

    // ---- logsig + LSTM 2 ----
    k_feats_f16_v2<<<100 * S2n, 256, 2 * C2 * sizeof(float)>>>(p_seq2, p_f2h, S1n, C2, S2n, IN2, IN2, seg2);
    {
        int smem = GF_STAGES * 2 * 128 * GF_LDA * (int)sizeof(__half);
        dim3 grid(768 / 128, (3000 + 127) / 128);
        k_gemm_f16<<<grid, 256, smem>>>(p_f2h, p_W2ih, bih2, bhh2, p_xp2, 3000, 768, IN2);
    }
    k_lstm2<<<50, 192>>>(p_xp2, p_WT2, p_y2, S2n);
    k_seg_stats<<<S2n, 256>>>(p_y2, p_ss2, S2n, C2);

    // ---- pooling + fc ----
    k_final<<<Nn, 256>>>(p_y2, p_ss2, bs2_g, bs2_b, fcW, fcb, out);
}